// round 11
// baseline (speedup 1.0000x reference)
#include <cuda_runtime.h>
#include <cuda_bf16.h>
#include <math.h>
#include <stdint.h>

#define NUM_HEADS 16
#define DHEAD 64
#define DE 128          // 2*DHEAD per head
#define DMODEL 1024
#define D2 2048
#define BB 4
#define NN 1024
#define MTOT (BB*NN)    // 4096
#define GP 36           // GEMM smem pitch
#define SSTG (128*GP)   // floats per GEMM stage per operand
#define WQK 68          // word pitch for bf16x2 Q/K arrays
#define VP  136         // float pitch for raw V tile
#define PP  68          // float pitch for P tiles

// Scratch (device globals; allocation APIs are forbidden)
__device__ float g_Q[(size_t)BB*NUM_HEADS*NN*DE];
__device__ float g_K[(size_t)BB*NUM_HEADS*NN*DE];
__device__ float g_V[(size_t)BB*NUM_HEADS*NN*DE];
__device__ float g_Oc[(size_t)BB*NN*D2];
__device__ float g_lam[NUM_HEADS];

__device__ __forceinline__ uint32_t f2tf(float f) {
    uint32_t u;
    asm("cvt.rna.tf32.f32 %0, %1;" : "=r"(u) : "f"(f));
    return u;
}

__device__ __forceinline__ void mma_tf32(float* d, const uint32_t* a, const uint32_t* b) {
    asm volatile(
        "mma.sync.aligned.m16n8k8.row.col.f32.tf32.tf32.f32 "
        "{%0,%1,%2,%3}, {%4,%5,%6,%7}, {%8,%9}, {%0,%1,%2,%3};"
        : "+f"(d[0]), "+f"(d[1]), "+f"(d[2]), "+f"(d[3])
        : "r"(a[0]), "r"(a[1]), "r"(a[2]), "r"(a[3]), "r"(b[0]), "r"(b[1]));
}

__device__ __forceinline__ void mma_bf16(float* d, const uint32_t* a, const uint32_t* b) {
    asm volatile(
        "mma.sync.aligned.m16n8k16.row.col.f32.bf16.bf16.f32 "
        "{%0,%1,%2,%3}, {%4,%5,%6,%7}, {%8,%9}, {%0,%1,%2,%3};"
        : "+f"(d[0]), "+f"(d[1]), "+f"(d[2]), "+f"(d[3])
        : "r"(a[0]), "r"(a[1]), "r"(a[2]), "r"(a[3]), "r"(b[0]), "r"(b[1]));
}

__device__ __forceinline__ uint32_t bf2u(__nv_bfloat162 v) {
    return *reinterpret_cast<uint32_t*>(&v);
}

__device__ __forceinline__ void split4(float4 v, uint2& h, uint2& l) {
    __nv_bfloat162 H0 = __floats2bfloat162_rn(v.x, v.y);
    __nv_bfloat162 H1 = __floats2bfloat162_rn(v.z, v.w);
    float2 f0 = __bfloat1622float2(H0);
    float2 f1 = __bfloat1622float2(H1);
    __nv_bfloat162 L0 = __floats2bfloat162_rn(v.x - f0.x, v.y - f0.y);
    __nv_bfloat162 L1 = __floats2bfloat162_rn(v.z - f1.x, v.w - f1.y);
    h = make_uint2(bf2u(H0), bf2u(H1));
    l = make_uint2(bf2u(L0), bf2u(L1));
}

// ---------------------------------------------------------------------------
// lambda[h]
// ---------------------------------------------------------------------------
__global__ void lambda_kernel(const float* __restrict__ lq1, const float* __restrict__ lk1,
                              const float* __restrict__ lq2, const float* __restrict__ lk2) {
    int w = threadIdx.x >> 5, lane = threadIdx.x & 31;
    int base = w * 64;
    float s1 = lq1[base+lane]*lk1[base+lane] + lq1[base+32+lane]*lk1[base+32+lane];
    float s2 = lq2[base+lane]*lk2[base+lane] + lq2[base+32+lane]*lk2[base+32+lane];
    #pragma unroll
    for (int off = 16; off; off >>= 1) {
        s1 += __shfl_xor_sync(0xffffffffu, s1, off);
        s2 += __shfl_xor_sync(0xffffffffu, s2, off);
    }
    if (lane == 0) g_lam[w] = expf(s1) - expf(s2) + 0.8f;
}

// ---------------------------------------------------------------------------
// tf32 tensor-core GEMM, cp.async double-buffered, ONE barrier per k-iter.
// 128x128x32 block tile. Raw fp32 staged async; cvt.rna.tf32 at fragment load
// (bit-identical to cvt-at-store). MODE 0: row-major C; MODE 1: QKV scatter.
// ---------------------------------------------------------------------------
template<int MODE>
__global__ __launch_bounds__(256, 2) void gemm_tf32(
    const float* __restrict__ A,
    const float* __restrict__ B0, const float* __restrict__ B1, const float* __restrict__ B2,
    float* __restrict__ C0, float* __restrict__ C1, float* __restrict__ C2,
    int K)
{
    extern __shared__ float gsm[];
    float* As = gsm;              // [2][SSTG]
    float* Bs = gsm + 2*SSTG;     // [2][SSTG]

    int t = threadIdx.x;
    int wid = t >> 5, lane = t & 31;
    int row0 = blockIdx.y * 128;

    const float* Bm;
    float* C;
    int col0;
    if (MODE == 1) {
        int which = blockIdx.x >> 4;
        col0 = (blockIdx.x & 15) * 128;
        Bm = (which == 0) ? B0 : ((which == 1) ? B1 : B2);
        C  = (which == 0) ? C0 : ((which == 1) ? C1 : C2);
    } else {
        col0 = blockIdx.x * 128;
        Bm = B0; C = C0;
    }

    uint32_t a_s0 = (uint32_t)__cvta_generic_to_shared(As);
    uint32_t b_s0 = (uint32_t)__cvta_generic_to_shared(Bs);

    // issue one 128x32 stage for both operands: 4 float4 chunks per thread each
    auto issue = [&](int s, int k0) {
        #pragma unroll
        for (int l = 0; l < 4; l++) {
            int idx = t + l*256;
            int r = idx >> 3, fq = (idx & 7) * 4;
            uint32_t da = a_s0 + (uint32_t)((s*SSTG + r*GP + fq) * 4);
            const float* sa = A + (size_t)(row0 + r) * K + k0 + fq;
            asm volatile("cp.async.cg.shared.global [%0], [%1], 16;" :: "r"(da), "l"(sa));
            uint32_t db = b_s0 + (uint32_t)((s*SSTG + r*GP + fq) * 4);
            const float* sb = Bm + (size_t)(col0 + r) * K + k0 + fq;
            asm volatile("cp.async.cg.shared.global [%0], [%1], 16;" :: "r"(db), "l"(sb));
        }
        asm volatile("cp.async.commit_group;" ::: "memory");
    };

    float acc[4][4][4];
    #pragma unroll
    for (int i = 0; i < 4; i++)
        #pragma unroll
        for (int j = 0; j < 4; j++)
            #pragma unroll
            for (int r = 0; r < 4; r++) acc[i][j][r] = 0.f;

    int wm = (wid & 1) * 64;
    int wn = (wid >> 1) * 32;
    int fr = lane >> 2;
    int fc = lane & 3;

    issue(0, 0);

    for (int k0 = 0; k0 < K; k0 += 32) {
        int s = (k0 >> 5) & 1;
        bool more = (k0 + 32 < K);

        asm volatile("cp.async.wait_group 0;" ::: "memory");
        __syncthreads();                 // current stage visible to all; prev mma done
        if (more) issue(s ^ 1, k0 + 32); // overlaps the mma below

        const float* Ab = As + s*SSTG;
        const float* Bb = Bs + s*SSTG;
        #pragma unroll
        for (int kc = 0; kc < 32; kc += 8) {
            uint32_t af[4][4], bf[4][2];
            #pragma unroll
            for (int i = 0; i < 4; i++) {
                af[i][0] = f2tf(Ab[(wm + i*16 +     fr)*GP + kc +     fc]);
                af[i][1] = f2tf(Ab[(wm + i*16 + 8 + fr)*GP + kc +     fc]);
                af[i][2] = f2tf(Ab[(wm + i*16 +     fr)*GP + kc + 4 + fc]);
                af[i][3] = f2tf(Ab[(wm + i*16 + 8 + fr)*GP + kc + 4 + fc]);
            }
            #pragma unroll
            for (int j = 0; j < 4; j++) {
                bf[j][0] = f2tf(Bb[(wn + j*8 + fr)*GP + kc +     fc]);
                bf[j][1] = f2tf(Bb[(wn + j*8 + fr)*GP + kc + 4 + fc]);
            }
            #pragma unroll
            for (int i = 0; i < 4; i++)
                #pragma unroll
                for (int j = 0; j < 4; j++)
                    mma_tf32(acc[i][j], af[i], bf[j]);
        }
    }

    __syncthreads();   // all mma done before epilogue overwrites nothing; harmless order point

    #pragma unroll
    for (int i = 0; i < 4; i++) {
        int rr = row0 + wm + i*16 + fr;
        #pragma unroll
        for (int j = 0; j < 4; j++) {
            int cc = col0 + wn + j*8 + fc*2;
            float2 v0 = make_float2(acc[i][j][0], acc[i][j][1]);
            float2 v1 = make_float2(acc[i][j][2], acc[i][j][3]);
            if (MODE == 0) {
                *(float2*)(C + (size_t)rr * DMODEL + cc) = v0;
                *(float2*)(C + (size_t)(rr + 8) * DMODEL + cc) = v1;
            } else {
                int h = cc >> 7, e = cc & 127;
                int bb = rr >> 10, n = rr & 1023;
                *(float2*)(C + (((size_t)(bb*NUM_HEADS + h) * NN + n) * DE + e)) = v0;
                int rr2 = rr + 8;
                bb = rr2 >> 10; n = rr2 & 1023;
                *(float2*)(C + (((size_t)(bb*NUM_HEADS + h) * NN + n) * DE + e)) = v1;
            }
        }
    }
}

#define GEMM_SMEM (4 * SSTG * 4)   // 73728 bytes

// ---------------------------------------------------------------------------
// Dual-stream flash attention (unchanged from R9, proven at 839 us):
// bf16 hi/lo logits, V overlaying K via cp.async, tf32 PV, deferred l, LPT.
// ---------------------------------------------------------------------------
__global__ __launch_bounds__(256, 2) void attn_kernel(const float* __restrict__ rms_scale) {
    extern __shared__ float sm[];
    uint32_t* Qh = (uint32_t*)sm;              // 64 x WQK words
    uint32_t* Ql = Qh + 64*WQK;
    uint32_t* Kh = Ql + 64*WQK;                // union with V
    uint32_t* Kl = Kh + 64*WQK;
    float*    Vs = (float*)Kh;                 // 64 x VP raw fp32
    float*    P1 = (float*)(Kl + 64*WQK);      // 64 x PP tf32
    float*    P2 = P1 + 64*PP;
    float*   bm1 = P2 + 64*PP;
    float*   bm2 = bm1 + 128;
    float*   bs1 = bm2 + 128;
    float*   bs2 = bs1 + 128;

    int t  = threadIdx.x;
    int bh = blockIdx.y;
    int h  = bh & (NUM_HEADS - 1);
    int b  = bh >> 4;
    int qi = gridDim.x - 1 - blockIdx.x;   // LPT
    int qb = qi * 64;
    const float* Qp = g_Q + (size_t)bh * NN * DE;
    const float* Kp = g_K + (size_t)bh * NN * DE;
    const float* Vp = g_V + (size_t)bh * NN * DE;

    int lane = t & 31, wid = t >> 5;
    int gid = lane >> 2, tig = lane & 3;
    int rt = (wid >> 1) * 16;
    int half = wid & 1;
    int ch = half * 32;
    int nh = half * 64;
    int rA = rt + gid, rB = rt + gid + 8;

    uint32_t vsm0 = (uint32_t)__cvta_generic_to_shared(Vs);

    #pragma unroll
    for (int l = 0; l < 8; l++) {
        int c = t + l*256;
        int r = c >> 5, dq = (c & 31) * 4;
        float4 q = *(const float4*)(Qp + (size_t)(qb + r)*DE + dq);
        uint2 hw, lw;
        split4(q, hw, lw);
        int wi = r*WQK + (dq >> 1);
        *(uint2*)&Qh[wi] = hw;
        *(uint2*)&Ql[wi] = lw;
    }

    float m1a = -1e30f, m1b = -1e30f, m2a = -1e30f, m2b = -1e30f;
    float l1a = 0.f, l1b = 0.f, l2a = 0.f, l2b = 0.f;
    float o1[8][4], o2[8][4];
    #pragma unroll
    for (int f = 0; f < 8; f++)
        #pragma unroll
        for (int r = 0; r < 4; r++) { o1[f][r] = 0.f; o2[f][r] = 0.f; }

    float lam = g_lam[h];

    int nkb = qi + 1;
    for (int jb = 0; jb < nkb; jb++) {
        int kb = jb * 64;

        #pragma unroll
        for (int l = 0; l < 8; l++) {
            int c = t + l*256;
            int r = c >> 5, dq = (c & 31) * 4;
            float4 kq = *(const float4*)(Kp + (size_t)(kb + r)*DE + dq);
            uint2 hw, lw;
            split4(kq, hw, lw);
            int wi = r*WQK + (dq >> 1);
            *(uint2*)&Kh[wi] = hw;
            *(uint2*)&Kl[wi] = lw;
        }
        __syncthreads();

        float s1[4][4], s2[4][4];
        #pragma unroll
        for (int i = 0; i < 4; i++)
            #pragma unroll
            for (int j = 0; j < 4; j++) { s1[i][j] = 0.f; s2[i][j] = 0.f; }

        #pragma unroll
        for (int kcw = 0; kcw < 4; kcw++) {
            int wb1 = kcw * 8;
            int wb2 = 32 + kcw * 8;
            uint32_t ah[4], al[4];
            ah[0] = Qh[rA*WQK + wb1 + tig];     ah[1] = Qh[rB*WQK + wb1 + tig];
            ah[2] = Qh[rA*WQK + wb1 + 4 + tig]; ah[3] = Qh[rB*WQK + wb1 + 4 + tig];
            al[0] = Ql[rA*WQK + wb1 + tig];     al[1] = Ql[rB*WQK + wb1 + tig];
            al[2] = Ql[rA*WQK + wb1 + 4 + tig]; al[3] = Ql[rB*WQK + wb1 + 4 + tig];
            #pragma unroll
            for (int nt = 0; nt < 4; nt++) {
                int n0 = ch + nt*8 + gid;
                uint32_t bhf[2], blf[2];
                bhf[0] = Kh[n0*WQK + wb1 + tig];
                bhf[1] = Kh[n0*WQK + wb1 + 4 + tig];
                blf[0] = Kl[n0*WQK + wb1 + tig];
                blf[1] = Kl[n0*WQK + wb1 + 4 + tig];
                mma_bf16(s1[nt], ah, bhf);
                mma_bf16(s1[nt], al, bhf);
                mma_bf16(s1[nt], ah, blf);
            }
            ah[0] = Qh[rA*WQK + wb2 + tig];     ah[1] = Qh[rB*WQK + wb2 + tig];
            ah[2] = Qh[rA*WQK + wb2 + 4 + tig]; ah[3] = Qh[rB*WQK + wb2 + 4 + tig];
            al[0] = Ql[rA*WQK + wb2 + tig];     al[1] = Ql[rB*WQK + wb2 + tig];
            al[2] = Ql[rA*WQK + wb2 + 4 + tig]; al[3] = Ql[rB*WQK + wb2 + 4 + tig];
            #pragma unroll
            for (int nt = 0; nt < 4; nt++) {
                int n0 = ch + nt*8 + gid;
                uint32_t bhf[2], blf[2];
                bhf[0] = Kh[n0*WQK + wb2 + tig];
                bhf[1] = Kh[n0*WQK + wb2 + 4 + tig];
                blf[0] = Kl[n0*WQK + wb2 + tig];
                blf[1] = Kl[n0*WQK + wb2 + 4 + tig];
                mma_bf16(s2[nt], ah, bhf);
                mma_bf16(s2[nt], al, bhf);
                mma_bf16(s2[nt], ah, blf);
            }
        }

        bool last = (jb == nkb - 1);
        #pragma unroll
        for (int nt = 0; nt < 4; nt++)
            #pragma unroll
            for (int c = 0; c < 4; c++) {
                float v1 = s1[nt][c] * 0.125f;
                float v2 = s2[nt][c] * 0.125f;
                if (last) {
                    int col = ch + nt*8 + 2*tig + (c & 1);
                    int row = rt + gid + ((c & 2) ? 8 : 0);
                    if (col > row) { v1 = -1e30f; v2 = -1e30f; }
                }
                s1[nt][c] = v1; s2[nt][c] = v2;
            }

        float mt1a = -1e30f, mt1b = -1e30f, mt2a = -1e30f, mt2b = -1e30f;
        #pragma unroll
        for (int nt = 0; nt < 4; nt++) {
            mt1a = fmaxf(mt1a, fmaxf(s1[nt][0], s1[nt][1]));
            mt1b = fmaxf(mt1b, fmaxf(s1[nt][2], s1[nt][3]));
            mt2a = fmaxf(mt2a, fmaxf(s2[nt][0], s2[nt][1]));
            mt2b = fmaxf(mt2b, fmaxf(s2[nt][2], s2[nt][3]));
        }
        #pragma unroll
        for (int off = 1; off <= 2; off <<= 1) {
            mt1a = fmaxf(mt1a, __shfl_xor_sync(0xffffffffu, mt1a, off));
            mt1b = fmaxf(mt1b, __shfl_xor_sync(0xffffffffu, mt1b, off));
            mt2a = fmaxf(mt2a, __shfl_xor_sync(0xffffffffu, mt2a, off));
            mt2b = fmaxf(mt2b, __shfl_xor_sync(0xffffffffu, mt2b, off));
        }
        if (tig == 0) {
            bm1[half*64 + rA] = mt1a; bm1[half*64 + rB] = mt1b;
            bm2[half*64 + rA] = mt2a; bm2[half*64 + rB] = mt2b;
        }
        __syncthreads();

        #pragma unroll
        for (int l = 0; l < 8; l++) {
            int c = t + l*256;
            int r = c >> 5, dq = (c & 31) * 4;
            uint32_t dst = vsm0 + (uint32_t)((r*VP + dq) * 4);
            const float* src = Vp + (size_t)(kb + r)*DE + dq;
            asm volatile("cp.async.cg.shared.global [%0], [%1], 16;" :: "r"(dst), "l"(src));
        }
        asm volatile("cp.async.commit_group;" ::: "memory");

        float M1a = fmaxf(m1a, fmaxf(bm1[rA], bm1[64 + rA]));
        float M1b = fmaxf(m1b, fmaxf(bm1[rB], bm1[64 + rB]));
        float M2a = fmaxf(m2a, fmaxf(bm2[rA], bm2[64 + rA]));
        float M2b = fmaxf(m2b, fmaxf(bm2[rB], bm2[64 + rB]));
        float c1a = __expf(m1a - M1a), c1b = __expf(m1b - M1b);
        float c2a = __expf(m2a - M2a), c2b = __expf(m2b - M2b);
        m1a = M1a; m1b = M1b; m2a = M2a; m2b = M2b;

        float ps1a = 0.f, ps1b = 0.f, ps2a = 0.f, ps2b = 0.f;
        #pragma unroll
        for (int nt = 0; nt < 4; nt++) {
            int colb = ch + nt*8 + 2*tig;
            float p0 = __uint_as_float(f2tf(__expf(s1[nt][0] - M1a)));
            float p1 = __uint_as_float(f2tf(__expf(s1[nt][1] - M1a)));
            float p2 = __uint_as_float(f2tf(__expf(s1[nt][2] - M1b)));
            float p3 = __uint_as_float(f2tf(__expf(s1[nt][3] - M1b)));
            ps1a += p0 + p1; ps1b += p2 + p3;
            *(float2*)&P1[rA*PP + colb] = make_float2(p0, p1);
            *(float2*)&P1[rB*PP + colb] = make_float2(p2, p3);
            float q0 = __uint_as_float(f2tf(__expf(s2[nt][0] - M2a)));
            float q1 = __uint_as_float(f2tf(__expf(s2[nt][1] - M2a)));
            float q2 = __uint_as_float(f2tf(__expf(s2[nt][2] - M2b)));
            float q3 = __uint_as_float(f2tf(__expf(s2[nt][3] - M2b)));
            ps2a += q0 + q1; ps2b += q2 + q3;
            *(float2*)&P2[rA*PP + colb] = make_float2(q0, q1);
            *(float2*)&P2[rB*PP + colb] = make_float2(q2, q3);
        }
        l1a = l1a*c1a + ps1a;
        l1b = l1b*c1b + ps1b;
        l2a = l2a*c2a + ps2a;
        l2b = l2b*c2b + ps2b;

        asm volatile("cp.async.wait_group 0;" ::: "memory");
        __syncthreads();

        #pragma unroll
        for (int f = 0; f < 8; f++) {
            o1[f][0] *= c1a; o1[f][1] *= c1a; o1[f][2] *= c1b; o1[f][3] *= c1b;
            o2[f][0] *= c2a; o2[f][1] *= c2a; o2[f][2] *= c2b; o2[f][3] *= c2b;
        }
        #pragma unroll
        for (int kc = 0; kc < 64; kc += 8) {
            uint32_t a1f[4], a2f[4];
            a1f[0] = __float_as_uint(P1[rA*PP + kc + tig]);
            a1f[1] = __float_as_uint(P1[rB*PP + kc + tig]);
            a1f[2] = __float_as_uint(P1[rA*PP + kc + tig + 4]);
            a1f[3] = __float_as_uint(P1[rB*PP + kc + tig + 4]);
            a2f[0] = __float_as_uint(P2[rA*PP + kc + tig]);
            a2f[1] = __float_as_uint(P2[rB*PP + kc + tig]);
            a2f[2] = __float_as_uint(P2[rA*PP + kc + tig + 4]);
            a2f[3] = __float_as_uint(P2[rB*PP + kc + tig + 4]);
            #pragma unroll
            for (int f = 0; f < 8; f++) {
                uint32_t bf[2];
                bf[0] = f2tf(Vs[(kc + tig    )*VP + nh + f*8 + gid]);
                bf[1] = f2tf(Vs[(kc + tig + 4)*VP + nh + f*8 + gid]);
                mma_tf32(o1[f], a1f, bf);
                mma_tf32(o2[f], a2f, bf);
            }
        }
        __syncthreads();
    }

    #pragma unroll
    for (int off = 1; off <= 2; off <<= 1) {
        l1a += __shfl_xor_sync(0xffffffffu, l1a, off);
        l1b += __shfl_xor_sync(0xffffffffu, l1b, off);
        l2a += __shfl_xor_sync(0xffffffffu, l2a, off);
        l2b += __shfl_xor_sync(0xffffffffu, l2b, off);
    }
    if (tig == 0) {
        bs1[half*64 + rA] = l1a; bs1[half*64 + rB] = l1b;
        bs2[half*64 + rA] = l2a; bs2[half*64 + rB] = l2b;
    }
    __syncthreads();
    float il1a = 1.0f / (bs1[rA] + bs1[64 + rA]);
    float il1b = 1.0f / (bs1[rB] + bs1[64 + rB]);
    float il2a = 1.0f / (bs2[rA] + bs2[64 + rA]);
    float il2b = 1.0f / (bs2[rB] + bs2[64 + rB]);

    float ssA = 0.f, ssB = 0.f;
    #pragma unroll
    for (int f = 0; f < 8; f++) {
        o1[f][0] = o1[f][0]*il1a - lam*o2[f][0]*il2a;
        o1[f][1] = o1[f][1]*il1a - lam*o2[f][1]*il2a;
        o1[f][2] = o1[f][2]*il1b - lam*o2[f][2]*il2b;
        o1[f][3] = o1[f][3]*il1b - lam*o2[f][3]*il2b;
        ssA += o1[f][0]*o1[f][0] + o1[f][1]*o1[f][1];
        ssB += o1[f][2]*o1[f][2] + o1[f][3]*o1[f][3];
    }
    ssA += __shfl_xor_sync(0xffffffffu, ssA, 1);
    ssA += __shfl_xor_sync(0xffffffffu, ssA, 2);
    ssB += __shfl_xor_sync(0xffffffffu, ssB, 1);
    ssB += __shfl_xor_sync(0xffffffffu, ssB, 2);

    if (tig == 0) {
        float* dst = half ? bm2 : bm1;
        dst[rA] = ssA;
        dst[rB] = ssB;
    }
    __syncthreads();
    float totA = bm1[rA] + bm2[rA];
    float totB = bm1[rB] + bm2[rB];
    float scA = rsqrtf(totA * (1.0f/128.0f) + 1e-5f) * 0.2f;
    float scB = rsqrtf(totB * (1.0f/128.0f) + 1e-5f) * 0.2f;

    size_t obaseA = ((size_t)b * NN + qb + rA) * D2 + h * DE;
    size_t obaseB = ((size_t)b * NN + qb + rB) * D2 + h * DE;
    #pragma unroll
    for (int f = 0; f < 8; f++) {
        int col = nh + f*8 + 2*tig;
        float2 rs = *(const float2*)(rms_scale + col);
        *(float2*)(g_Oc + obaseA + col) = make_float2(o1[f][0]*scA*rs.x, o1[f][1]*scA*rs.y);
        *(float2*)(g_Oc + obaseB + col) = make_float2(o1[f][2]*scB*rs.x, o1[f][3]*scB*rs.y);
    }
}

#define ATTN_SMEM (26624 * 4)   // 106496 bytes -> 2 blocks/SM

extern "C" void kernel_launch(void* const* d_in, const int* in_sizes, int n_in,
                              void* d_out, int out_size) {
    const float* X   = (const float*)d_in[0];
    const float* Wq  = (const float*)d_in[1];
    const float* Wk  = (const float*)d_in[2];
    const float* Wv  = (const float*)d_in[3];
    const float* Wo  = (const float*)d_in[4];
    const float* lq1 = (const float*)d_in[5];
    const float* lk1 = (const float*)d_in[6];
    const float* lq2 = (const float*)d_in[7];
    const float* lk2 = (const float*)d_in[8];
    const float* rms = (const float*)d_in[9];

    float *pQ, *pK, *pV, *pOc;
    cudaGetSymbolAddress((void**)&pQ,  g_Q);
    cudaGetSymbolAddress((void**)&pK,  g_K);
    cudaGetSymbolAddress((void**)&pV,  g_V);
    cudaGetSymbolAddress((void**)&pOc, g_Oc);

    lambda_kernel<<<1, 512>>>(lq1, lk1, lq2, lk2);

    cudaFuncSetAttribute(gemm_tf32<1>, cudaFuncAttributeMaxDynamicSharedMemorySize, GEMM_SMEM);
    cudaFuncSetAttribute(gemm_tf32<0>, cudaFuncAttributeMaxDynamicSharedMemorySize, GEMM_SMEM);

    dim3 gqkv(48, MTOT/128);
    gemm_tf32<1><<<gqkv, 256, GEMM_SMEM>>>(X, Wq, Wk, Wv, pQ, pK, pV, DMODEL);

    cudaFuncSetAttribute(attn_kernel, cudaFuncAttributeMaxDynamicSharedMemorySize, ATTN_SMEM);
    attn_kernel<<<dim3(NN/64, BB*NUM_HEADS), 256, ATTN_SMEM>>>(rms);

    dim3 gout(DMODEL/128, MTOT/128);
    gemm_tf32<0><<<gout, 256, GEMM_SMEM>>>(pOc, Wo, nullptr, nullptr, (float*)d_out, nullptr, nullptr, D2);
}

// round 13
// speedup vs baseline: 1.0518x; 1.0518x over previous
#include <cuda_runtime.h>
#include <cuda_bf16.h>
#include <math.h>
#include <stdint.h>

#define NUM_HEADS 16
#define DHEAD 64
#define DE 128          // 2*DHEAD per head
#define DMODEL 1024
#define D2 2048
#define BB 4
#define NN 1024
#define MTOT (BB*NN)    // 4096
#define GP 36           // GEMM smem pitch
#define SSTG (128*GP)   // floats per GEMM stage per operand
#define WQK 68          // word pitch for bf16x2 Q/K arrays
#define VP  136         // float pitch for raw V tile
#define PP  68          // float pitch for P tiles

// Scratch (device globals; allocation APIs are forbidden)
__device__ float g_Q[(size_t)BB*NUM_HEADS*NN*DE];
__device__ float g_K[(size_t)BB*NUM_HEADS*NN*DE];
__device__ float g_V[(size_t)BB*NUM_HEADS*NN*DE];
__device__ float g_Oc[(size_t)BB*NN*D2];
__device__ float g_lam[NUM_HEADS];

__device__ __forceinline__ uint32_t f2tf(float f) {
    uint32_t u;
    asm("cvt.rna.tf32.f32 %0, %1;" : "=r"(u) : "f"(f));
    return u;
}

__device__ __forceinline__ void mma_tf32(float* d, const uint32_t* a, const uint32_t* b) {
    asm volatile(
        "mma.sync.aligned.m16n8k8.row.col.f32.tf32.tf32.f32 "
        "{%0,%1,%2,%3}, {%4,%5,%6,%7}, {%8,%9}, {%0,%1,%2,%3};"
        : "+f"(d[0]), "+f"(d[1]), "+f"(d[2]), "+f"(d[3])
        : "r"(a[0]), "r"(a[1]), "r"(a[2]), "r"(a[3]), "r"(b[0]), "r"(b[1]));
}

__device__ __forceinline__ void mma_bf16(float* d, const uint32_t* a, const uint32_t* b) {
    asm volatile(
        "mma.sync.aligned.m16n8k16.row.col.f32.bf16.bf16.f32 "
        "{%0,%1,%2,%3}, {%4,%5,%6,%7}, {%8,%9}, {%0,%1,%2,%3};"
        : "+f"(d[0]), "+f"(d[1]), "+f"(d[2]), "+f"(d[3])
        : "r"(a[0]), "r"(a[1]), "r"(a[2]), "r"(a[3]), "r"(b[0]), "r"(b[1]));
}

__device__ __forceinline__ uint32_t bf2u(__nv_bfloat162 v) {
    return *reinterpret_cast<uint32_t*>(&v);
}

__device__ __forceinline__ void split4(float4 v, uint2& h, uint2& l) {
    __nv_bfloat162 H0 = __floats2bfloat162_rn(v.x, v.y);
    __nv_bfloat162 H1 = __floats2bfloat162_rn(v.z, v.w);
    float2 f0 = __bfloat1622float2(H0);
    float2 f1 = __bfloat1622float2(H1);
    __nv_bfloat162 L0 = __floats2bfloat162_rn(v.x - f0.x, v.y - f0.y);
    __nv_bfloat162 L1 = __floats2bfloat162_rn(v.z - f1.x, v.w - f1.y);
    h = make_uint2(bf2u(H0), bf2u(H1));
    l = make_uint2(bf2u(L0), bf2u(L1));
}

// ---------------------------------------------------------------------------
// lambda[h]
// ---------------------------------------------------------------------------
__global__ void lambda_kernel(const float* __restrict__ lq1, const float* __restrict__ lk1,
                              const float* __restrict__ lq2, const float* __restrict__ lk2) {
    int w = threadIdx.x >> 5, lane = threadIdx.x & 31;
    int base = w * 64;
    float s1 = lq1[base+lane]*lk1[base+lane] + lq1[base+32+lane]*lk1[base+32+lane];
    float s2 = lq2[base+lane]*lk2[base+lane] + lq2[base+32+lane]*lk2[base+32+lane];
    #pragma unroll
    for (int off = 16; off; off >>= 1) {
        s1 += __shfl_xor_sync(0xffffffffu, s1, off);
        s2 += __shfl_xor_sync(0xffffffffu, s2, off);
    }
    if (lane == 0) g_lam[w] = expf(s1) - expf(s2) + 0.8f;
}

// ---------------------------------------------------------------------------
// tf32 tensor-core GEMM: R5 dataflow (register prefetch, cvt-at-store)
// + double-buffered smem at BK=32 -> ONE barrier per k-iter.
// Stores hit stage s^1 while mma reads stage s; barrier separates iter-i
// reads of s from iter-(i+1) writes of s. Arithmetic bit-identical to R5.
// ---------------------------------------------------------------------------
template<int MODE>
__global__ __launch_bounds__(256, 2) void gemm_tf32(
    const float* __restrict__ A,
    const float* __restrict__ B0, const float* __restrict__ B1, const float* __restrict__ B2,
    float* __restrict__ C0, float* __restrict__ C1, float* __restrict__ C2,
    int K)
{
    extern __shared__ float gsm[];
    float* Asb = gsm;              // [2][SSTG]
    float* Bsb = gsm + 2*SSTG;     // [2][SSTG]

    int t = threadIdx.x;
    int wid = t >> 5, lane = t & 31;
    int row0 = blockIdx.y * 128;

    const float* Bm;
    float* C;
    int col0;
    if (MODE == 1) {
        int which = blockIdx.x >> 4;
        col0 = (blockIdx.x & 15) * 128;
        Bm = (which == 0) ? B0 : ((which == 1) ? B1 : B2);
        C  = (which == 0) ? C0 : ((which == 1) ? C1 : C2);
    } else {
        col0 = blockIdx.x * 128;
        Bm = B0; C = C0;
    }

    int r0 = t >> 3;
    int kq = (t & 7) * 4;
    const float* Ag = A  + (size_t)(row0 + r0) * K + kq;
    const float* Bg = Bm + (size_t)(col0 + r0) * K + kq;

    float4 ar[4], br[4];
    #pragma unroll
    for (int l = 0; l < 4; l++) {
        ar[l] = *(const float4*)(Ag + (size_t)l * 32 * K);
        br[l] = *(const float4*)(Bg + (size_t)l * 32 * K);
    }

    // store stage 0 (cvt at store, same as R5)
    #pragma unroll
    for (int l = 0; l < 4; l++) {
        uint4 ua = make_uint4(f2tf(ar[l].x), f2tf(ar[l].y), f2tf(ar[l].z), f2tf(ar[l].w));
        *(uint4*)&Asb[(r0 + l*32)*GP + kq] = ua;
        uint4 ub = make_uint4(f2tf(br[l].x), f2tf(br[l].y), f2tf(br[l].z), f2tf(br[l].w));
        *(uint4*)&Bsb[(r0 + l*32)*GP + kq] = ub;
    }
    __syncthreads();

    float acc[4][4][4];
    #pragma unroll
    for (int i = 0; i < 4; i++)
        #pragma unroll
        for (int j = 0; j < 4; j++)
            #pragma unroll
            for (int r = 0; r < 4; r++) acc[i][j][r] = 0.f;

    int wm = (wid & 1) * 64;
    int wn = (wid >> 1) * 32;
    int fr = lane >> 2;
    int fc = lane & 3;

    for (int k0 = 0; k0 < K; k0 += 32) {
        int s = (k0 >> 5) & 1;
        bool more = (k0 + 32 < K);

        // prefetch next k-tile into registers (overlaps the mma below)
        if (more) {
            #pragma unroll
            for (int l = 0; l < 4; l++) {
                ar[l] = *(const float4*)(Ag + (size_t)l * 32 * K + k0 + 32);
                br[l] = *(const float4*)(Bg + (size_t)l * 32 * K + k0 + 32);
            }
        }

        const float* Ab = Asb + s*SSTG;
        const float* Bb = Bsb + s*SSTG;
        #pragma unroll
        for (int kc = 0; kc < 32; kc += 8) {
            uint32_t af[4][4], bf[4][2];
            #pragma unroll
            for (int i = 0; i < 4; i++) {
                af[i][0] = __float_as_uint(Ab[(wm + i*16 +     fr)*GP + kc +     fc]);
                af[i][1] = __float_as_uint(Ab[(wm + i*16 + 8 + fr)*GP + kc +     fc]);
                af[i][2] = __float_as_uint(Ab[(wm + i*16 +     fr)*GP + kc + 4 + fc]);
                af[i][3] = __float_as_uint(Ab[(wm + i*16 + 8 + fr)*GP + kc + 4 + fc]);
            }
            #pragma unroll
            for (int j = 0; j < 4; j++) {
                bf[j][0] = __float_as_uint(Bb[(wn + j*8 + fr)*GP + kc +     fc]);
                bf[j][1] = __float_as_uint(Bb[(wn + j*8 + fr)*GP + kc + 4 + fc]);
            }
            #pragma unroll
            for (int i = 0; i < 4; i++)
                #pragma unroll
                for (int j = 0; j < 4; j++)
                    mma_tf32(acc[i][j], af[i], bf[j]);
        }

        // store next tile into the OTHER stage (no conflict with mma above)
        if (more) {
            float* An = Asb + (s^1)*SSTG;
            float* Bn = Bsb + (s^1)*SSTG;
            #pragma unroll
            for (int l = 0; l < 4; l++) {
                uint4 ua = make_uint4(f2tf(ar[l].x), f2tf(ar[l].y), f2tf(ar[l].z), f2tf(ar[l].w));
                *(uint4*)&An[(r0 + l*32)*GP + kq] = ua;
                uint4 ub = make_uint4(f2tf(br[l].x), f2tf(br[l].y), f2tf(br[l].z), f2tf(br[l].w));
                *(uint4*)&Bn[(r0 + l*32)*GP + kq] = ub;
            }
        }
        __syncthreads();   // ONE barrier per iter
    }

    #pragma unroll
    for (int i = 0; i < 4; i++) {
        int rr = row0 + wm + i*16 + fr;
        #pragma unroll
        for (int j = 0; j < 4; j++) {
            int cc = col0 + wn + j*8 + fc*2;
            float2 v0 = make_float2(acc[i][j][0], acc[i][j][1]);
            float2 v1 = make_float2(acc[i][j][2], acc[i][j][3]);
            if (MODE == 0) {
                *(float2*)(C + (size_t)rr * DMODEL + cc) = v0;
                *(float2*)(C + (size_t)(rr + 8) * DMODEL + cc) = v1;
            } else {
                int h = cc >> 7, e = cc & 127;
                int bb = rr >> 10, n = rr & 1023;
                *(float2*)(C + (((size_t)(bb*NUM_HEADS + h) * NN + n) * DE + e)) = v0;
                int rr2 = rr + 8;
                bb = rr2 >> 10; n = rr2 & 1023;
                *(float2*)(C + (((size_t)(bb*NUM_HEADS + h) * NN + n) * DE + e)) = v1;
            }
        }
    }
}

#define GEMM_SMEM (4 * SSTG * 4)   // 73728 bytes

// ---------------------------------------------------------------------------
// Dual-stream flash attention (unchanged from R9, proven at 839 us):
// bf16 hi/lo logits, V overlaying K via cp.async, tf32 PV, deferred l, LPT.
// ---------------------------------------------------------------------------
__global__ __launch_bounds__(256, 2) void attn_kernel(const float* __restrict__ rms_scale) {
    extern __shared__ float sm[];
    uint32_t* Qh = (uint32_t*)sm;              // 64 x WQK words
    uint32_t* Ql = Qh + 64*WQK;
    uint32_t* Kh = Ql + 64*WQK;                // union with V
    uint32_t* Kl = Kh + 64*WQK;
    float*    Vs = (float*)Kh;                 // 64 x VP raw fp32
    float*    P1 = (float*)(Kl + 64*WQK);      // 64 x PP tf32
    float*    P2 = P1 + 64*PP;
    float*   bm1 = P2 + 64*PP;
    float*   bm2 = bm1 + 128;
    float*   bs1 = bm2 + 128;
    float*   bs2 = bs1 + 128;

    int t  = threadIdx.x;
    int bh = blockIdx.y;
    int h  = bh & (NUM_HEADS - 1);
    int b  = bh >> 4;
    int qi = gridDim.x - 1 - blockIdx.x;   // LPT
    int qb = qi * 64;
    const float* Qp = g_Q + (size_t)bh * NN * DE;
    const float* Kp = g_K + (size_t)bh * NN * DE;
    const float* Vp = g_V + (size_t)bh * NN * DE;

    int lane = t & 31, wid = t >> 5;
    int gid = lane >> 2, tig = lane & 3;
    int rt = (wid >> 1) * 16;
    int half = wid & 1;
    int ch = half * 32;
    int nh = half * 64;
    int rA = rt + gid, rB = rt + gid + 8;

    uint32_t vsm0 = (uint32_t)__cvta_generic_to_shared(Vs);

    #pragma unroll
    for (int l = 0; l < 8; l++) {
        int c = t + l*256;
        int r = c >> 5, dq = (c & 31) * 4;
        float4 q = *(const float4*)(Qp + (size_t)(qb + r)*DE + dq);
        uint2 hw, lw;
        split4(q, hw, lw);
        int wi = r*WQK + (dq >> 1);
        *(uint2*)&Qh[wi] = hw;
        *(uint2*)&Ql[wi] = lw;
    }

    float m1a = -1e30f, m1b = -1e30f, m2a = -1e30f, m2b = -1e30f;
    float l1a = 0.f, l1b = 0.f, l2a = 0.f, l2b = 0.f;
    float o1[8][4], o2[8][4];
    #pragma unroll
    for (int f = 0; f < 8; f++)
        #pragma unroll
        for (int r = 0; r < 4; r++) { o1[f][r] = 0.f; o2[f][r] = 0.f; }

    float lam = g_lam[h];

    int nkb = qi + 1;
    for (int jb = 0; jb < nkb; jb++) {
        int kb = jb * 64;

        #pragma unroll
        for (int l = 0; l < 8; l++) {
            int c = t + l*256;
            int r = c >> 5, dq = (c & 31) * 4;
            float4 kq = *(const float4*)(Kp + (size_t)(kb + r)*DE + dq);
            uint2 hw, lw;
            split4(kq, hw, lw);
            int wi = r*WQK + (dq >> 1);
            *(uint2*)&Kh[wi] = hw;
            *(uint2*)&Kl[wi] = lw;
        }
        __syncthreads();

        float s1[4][4], s2[4][4];
        #pragma unroll
        for (int i = 0; i < 4; i++)
            #pragma unroll
            for (int j = 0; j < 4; j++) { s1[i][j] = 0.f; s2[i][j] = 0.f; }

        #pragma unroll
        for (int kcw = 0; kcw < 4; kcw++) {
            int wb1 = kcw * 8;
            int wb2 = 32 + kcw * 8;
            uint32_t ah[4], al[4];
            ah[0] = Qh[rA*WQK + wb1 + tig];     ah[1] = Qh[rB*WQK + wb1 + tig];
            ah[2] = Qh[rA*WQK + wb1 + 4 + tig]; ah[3] = Qh[rB*WQK + wb1 + 4 + tig];
            al[0] = Ql[rA*WQK + wb1 + tig];     al[1] = Ql[rB*WQK + wb1 + tig];
            al[2] = Ql[rA*WQK + wb1 + 4 + tig]; al[3] = Ql[rB*WQK + wb1 + 4 + tig];
            #pragma unroll
            for (int nt = 0; nt < 4; nt++) {
                int n0 = ch + nt*8 + gid;
                uint32_t bhf[2], blf[2];
                bhf[0] = Kh[n0*WQK + wb1 + tig];
                bhf[1] = Kh[n0*WQK + wb1 + 4 + tig];
                blf[0] = Kl[n0*WQK + wb1 + tig];
                blf[1] = Kl[n0*WQK + wb1 + 4 + tig];
                mma_bf16(s1[nt], ah, bhf);
                mma_bf16(s1[nt], al, bhf);
                mma_bf16(s1[nt], ah, blf);
            }
            ah[0] = Qh[rA*WQK + wb2 + tig];     ah[1] = Qh[rB*WQK + wb2 + tig];
            ah[2] = Qh[rA*WQK + wb2 + 4 + tig]; ah[3] = Qh[rB*WQK + wb2 + 4 + tig];
            al[0] = Ql[rA*WQK + wb2 + tig];     al[1] = Ql[rB*WQK + wb2 + tig];
            al[2] = Ql[rA*WQK + wb2 + 4 + tig]; al[3] = Ql[rB*WQK + wb2 + 4 + tig];
            #pragma unroll
            for (int nt = 0; nt < 4; nt++) {
                int n0 = ch + nt*8 + gid;
                uint32_t bhf[2], blf[2];
                bhf[0] = Kh[n0*WQK + wb2 + tig];
                bhf[1] = Kh[n0*WQK + wb2 + 4 + tig];
                blf[0] = Kl[n0*WQK + wb2 + tig];
                blf[1] = Kl[n0*WQK + wb2 + 4 + tig];
                mma_bf16(s2[nt], ah, bhf);
                mma_bf16(s2[nt], al, bhf);
                mma_bf16(s2[nt], ah, blf);
            }
        }

        bool last = (jb == nkb - 1);
        #pragma unroll
        for (int nt = 0; nt < 4; nt++)
            #pragma unroll
            for (int c = 0; c < 4; c++) {
                float v1 = s1[nt][c] * 0.125f;
                float v2 = s2[nt][c] * 0.125f;
                if (last) {
                    int col = ch + nt*8 + 2*tig + (c & 1);
                    int row = rt + gid + ((c & 2) ? 8 : 0);
                    if (col > row) { v1 = -1e30f; v2 = -1e30f; }
                }
                s1[nt][c] = v1; s2[nt][c] = v2;
            }

        float mt1a = -1e30f, mt1b = -1e30f, mt2a = -1e30f, mt2b = -1e30f;
        #pragma unroll
        for (int nt = 0; nt < 4; nt++) {
            mt1a = fmaxf(mt1a, fmaxf(s1[nt][0], s1[nt][1]));
            mt1b = fmaxf(mt1b, fmaxf(s1[nt][2], s1[nt][3]));
            mt2a = fmaxf(mt2a, fmaxf(s2[nt][0], s2[nt][1]));
            mt2b = fmaxf(mt2b, fmaxf(s2[nt][2], s2[nt][3]));
        }
        #pragma unroll
        for (int off = 1; off <= 2; off <<= 1) {
            mt1a = fmaxf(mt1a, __shfl_xor_sync(0xffffffffu, mt1a, off));
            mt1b = fmaxf(mt1b, __shfl_xor_sync(0xffffffffu, mt1b, off));
            mt2a = fmaxf(mt2a, __shfl_xor_sync(0xffffffffu, mt2a, off));
            mt2b = fmaxf(mt2b, __shfl_xor_sync(0xffffffffu, mt2b, off));
        }
        if (tig == 0) {
            bm1[half*64 + rA] = mt1a; bm1[half*64 + rB] = mt1b;
            bm2[half*64 + rA] = mt2a; bm2[half*64 + rB] = mt2b;
        }
        __syncthreads();

        #pragma unroll
        for (int l = 0; l < 8; l++) {
            int c = t + l*256;
            int r = c >> 5, dq = (c & 31) * 4;
            uint32_t dst = vsm0 + (uint32_t)((r*VP + dq) * 4);
            const float* src = Vp + (size_t)(kb + r)*DE + dq;
            asm volatile("cp.async.cg.shared.global [%0], [%1], 16;" :: "r"(dst), "l"(src));
        }
        asm volatile("cp.async.commit_group;" ::: "memory");

        float M1a = fmaxf(m1a, fmaxf(bm1[rA], bm1[64 + rA]));
        float M1b = fmaxf(m1b, fmaxf(bm1[rB], bm1[64 + rB]));
        float M2a = fmaxf(m2a, fmaxf(bm2[rA], bm2[64 + rA]));
        float M2b = fmaxf(m2b, fmaxf(bm2[rB], bm2[64 + rB]));
        float c1a = __expf(m1a - M1a), c1b = __expf(m1b - M1b);
        float c2a = __expf(m2a - M2a), c2b = __expf(m2b - M2b);
        m1a = M1a; m1b = M1b; m2a = M2a; m2b = M2b;

        float ps1a = 0.f, ps1b = 0.f, ps2a = 0.f, ps2b = 0.f;
        #pragma unroll
        for (int nt = 0; nt < 4; nt++) {
            int colb = ch + nt*8 + 2*tig;
            float p0 = __uint_as_float(f2tf(__expf(s1[nt][0] - M1a)));
            float p1 = __uint_as_float(f2tf(__expf(s1[nt][1] - M1a)));
            float p2 = __uint_as_float(f2tf(__expf(s1[nt][2] - M1b)));
            float p3 = __uint_as_float(f2tf(__expf(s1[nt][3] - M1b)));
            ps1a += p0 + p1; ps1b += p2 + p3;
            *(float2*)&P1[rA*PP + colb] = make_float2(p0, p1);
            *(float2*)&P1[rB*PP + colb] = make_float2(p2, p3);
            float q0 = __uint_as_float(f2tf(__expf(s2[nt][0] - M2a)));
            float q1 = __uint_as_float(f2tf(__expf(s2[nt][1] - M2a)));
            float q2 = __uint_as_float(f2tf(__expf(s2[nt][2] - M2b)));
            float q3 = __uint_as_float(f2tf(__expf(s2[nt][3] - M2b)));
            ps2a += q0 + q1; ps2b += q2 + q3;
            *(float2*)&P2[rA*PP + colb] = make_float2(q0, q1);
            *(float2*)&P2[rB*PP + colb] = make_float2(q2, q3);
        }
        l1a = l1a*c1a + ps1a;
        l1b = l1b*c1b + ps1b;
        l2a = l2a*c2a + ps2a;
        l2b = l2b*c2b + ps2b;

        asm volatile("cp.async.wait_group 0;" ::: "memory");
        __syncthreads();

        #pragma unroll
        for (int f = 0; f < 8; f++) {
            o1[f][0] *= c1a; o1[f][1] *= c1a; o1[f][2] *= c1b; o1[f][3] *= c1b;
            o2[f][0] *= c2a; o2[f][1] *= c2a; o2[f][2] *= c2b; o2[f][3] *= c2b;
        }
        #pragma unroll
        for (int kc = 0; kc < 64; kc += 8) {
            uint32_t a1f[4], a2f[4];
            a1f[0] = __float_as_uint(P1[rA*PP + kc + tig]);
            a1f[1] = __float_as_uint(P1[rB*PP + kc + tig]);
            a1f[2] = __float_as_uint(P1[rA*PP + kc + tig + 4]);
            a1f[3] = __float_as_uint(P1[rB*PP + kc + tig + 4]);
            a2f[0] = __float_as_uint(P2[rA*PP + kc + tig]);
            a2f[1] = __float_as_uint(P2[rB*PP + kc + tig]);
            a2f[2] = __float_as_uint(P2[rA*PP + kc + tig + 4]);
            a2f[3] = __float_as_uint(P2[rB*PP + kc + tig + 4]);
            #pragma unroll
            for (int f = 0; f < 8; f++) {
                uint32_t bf[2];
                bf[0] = f2tf(Vs[(kc + tig    )*VP + nh + f*8 + gid]);
                bf[1] = f2tf(Vs[(kc + tig + 4)*VP + nh + f*8 + gid]);
                mma_tf32(o1[f], a1f, bf);
                mma_tf32(o2[f], a2f, bf);
            }
        }
        __syncthreads();
    }

    #pragma unroll
    for (int off = 1; off <= 2; off <<= 1) {
        l1a += __shfl_xor_sync(0xffffffffu, l1a, off);
        l1b += __shfl_xor_sync(0xffffffffu, l1b, off);
        l2a += __shfl_xor_sync(0xffffffffu, l2a, off);
        l2b += __shfl_xor_sync(0xffffffffu, l2b, off);
    }
    if (tig == 0) {
        bs1[half*64 + rA] = l1a; bs1[half*64 + rB] = l1b;
        bs2[half*64 + rA] = l2a; bs2[half*64 + rB] = l2b;
    }
    __syncthreads();
    float il1a = 1.0f / (bs1[rA] + bs1[64 + rA]);
    float il1b = 1.0f / (bs1[rB] + bs1[64 + rB]);
    float il2a = 1.0f / (bs2[rA] + bs2[64 + rA]);
    float il2b = 1.0f / (bs2[rB] + bs2[64 + rB]);

    float ssA = 0.f, ssB = 0.f;
    #pragma unroll
    for (int f = 0; f < 8; f++) {
        o1[f][0] = o1[f][0]*il1a - lam*o2[f][0]*il2a;
        o1[f][1] = o1[f][1]*il1a - lam*o2[f][1]*il2a;
        o1[f][2] = o1[f][2]*il1b - lam*o2[f][2]*il2b;
        o1[f][3] = o1[f][3]*il1b - lam*o2[f][3]*il2b;
        ssA += o1[f][0]*o1[f][0] + o1[f][1]*o1[f][1];
        ssB += o1[f][2]*o1[f][2] + o1[f][3]*o1[f][3];
    }
    ssA += __shfl_xor_sync(0xffffffffu, ssA, 1);
    ssA += __shfl_xor_sync(0xffffffffu, ssA, 2);
    ssB += __shfl_xor_sync(0xffffffffu, ssB, 1);
    ssB += __shfl_xor_sync(0xffffffffu, ssB, 2);

    if (tig == 0) {
        float* dst = half ? bm2 : bm1;
        dst[rA] = ssA;
        dst[rB] = ssB;
    }
    __syncthreads();
    float totA = bm1[rA] + bm2[rA];
    float totB = bm1[rB] + bm2[rB];
    float scA = rsqrtf(totA * (1.0f/128.0f) + 1e-5f) * 0.2f;
    float scB = rsqrtf(totB * (1.0f/128.0f) + 1e-5f) * 0.2f;

    size_t obaseA = ((size_t)b * NN + qb + rA) * D2 + h * DE;
    size_t obaseB = ((size_t)b * NN + qb + rB) * D2 + h * DE;
    #pragma unroll
    for (int f = 0; f < 8; f++) {
        int col = nh + f*8 + 2*tig;
        float2 rs = *(const float2*)(rms_scale + col);
        *(float2*)(g_Oc + obaseA + col) = make_float2(o1[f][0]*scA*rs.x, o1[f][1]*scA*rs.y);
        *(float2*)(g_Oc + obaseB + col) = make_float2(o1[f][2]*scB*rs.x, o1[f][3]*scB*rs.y);
    }
}

#define ATTN_SMEM (26624 * 4)   // 106496 bytes -> 2 blocks/SM

extern "C" void kernel_launch(void* const* d_in, const int* in_sizes, int n_in,
                              void* d_out, int out_size) {
    const float* X   = (const float*)d_in[0];
    const float* Wq  = (const float*)d_in[1];
    const float* Wk  = (const float*)d_in[2];
    const float* Wv  = (const float*)d_in[3];
    const float* Wo  = (const float*)d_in[4];
    const float* lq1 = (const float*)d_in[5];
    const float* lk1 = (const float*)d_in[6];
    const float* lq2 = (const float*)d_in[7];
    const float* lk2 = (const float*)d_in[8];
    const float* rms = (const float*)d_in[9];

    float *pQ, *pK, *pV, *pOc;
    cudaGetSymbolAddress((void**)&pQ,  g_Q);
    cudaGetSymbolAddress((void**)&pK,  g_K);
    cudaGetSymbolAddress((void**)&pV,  g_V);
    cudaGetSymbolAddress((void**)&pOc, g_Oc);

    lambda_kernel<<<1, 512>>>(lq1, lk1, lq2, lk2);

    cudaFuncSetAttribute(gemm_tf32<1>, cudaFuncAttributeMaxDynamicSharedMemorySize, GEMM_SMEM);
    cudaFuncSetAttribute(gemm_tf32<0>, cudaFuncAttributeMaxDynamicSharedMemorySize, GEMM_SMEM);

    dim3 gqkv(48, MTOT/128);
    gemm_tf32<1><<<gqkv, 256, GEMM_SMEM>>>(X, Wq, Wk, Wv, pQ, pK, pV, DMODEL);

    cudaFuncSetAttribute(attn_kernel, cudaFuncAttributeMaxDynamicSharedMemorySize, ATTN_SMEM);
    attn_kernel<<<dim3(NN/64, BB*NUM_HEADS), 256, ATTN_SMEM>>>(rms);

    dim3 gout(DMODEL/128, MTOT/128);
    gemm_tf32<0><<<gout, 256, GEMM_SMEM>>>(pOc, Wo, nullptr, nullptr, (float*)d_out, nullptr, nullptr, D2);
}

// round 15
// speedup vs baseline: 1.0770x; 1.0240x over previous
#include <cuda_runtime.h>
#include <cuda_bf16.h>
#include <math.h>
#include <stdint.h>

#define NUM_HEADS 16
#define DHEAD 64
#define DE 128          // 2*DHEAD per head
#define DMODEL 1024
#define D2 2048
#define BB 4
#define NN 1024
#define MTOT (BB*NN)    // 4096
#define GP 36           // GEMM smem pitch (144B rows: ldmatrix rows land on banks 0,16,...,112 -> conflict-free)
#define WQK 68          // word pitch for bf16x2 Q/K arrays (attention)
#define VP  136         // float pitch for raw V tile (attention)
#define PP  68          // float pitch for P tiles (attention)

// Scratch (device globals; allocation APIs are forbidden)
__device__ float g_Q[(size_t)BB*NUM_HEADS*NN*DE];
__device__ float g_K[(size_t)BB*NUM_HEADS*NN*DE];
__device__ float g_V[(size_t)BB*NUM_HEADS*NN*DE];
__device__ float g_Oc[(size_t)BB*NN*D2];
__device__ float g_lam[NUM_HEADS];

__device__ __forceinline__ uint32_t f2tf(float f) {
    uint32_t u;
    asm("cvt.rna.tf32.f32 %0, %1;" : "=r"(u) : "f"(f));
    return u;
}

__device__ __forceinline__ void mma_tf32(float* d, const uint32_t* a, const uint32_t* b) {
    asm volatile(
        "mma.sync.aligned.m16n8k8.row.col.f32.tf32.tf32.f32 "
        "{%0,%1,%2,%3}, {%4,%5,%6,%7}, {%8,%9}, {%0,%1,%2,%3};"
        : "+f"(d[0]), "+f"(d[1]), "+f"(d[2]), "+f"(d[3])
        : "r"(a[0]), "r"(a[1]), "r"(a[2]), "r"(a[3]), "r"(b[0]), "r"(b[1]));
}

__device__ __forceinline__ void mma_bf16(float* d, const uint32_t* a, const uint32_t* b) {
    asm volatile(
        "mma.sync.aligned.m16n8k16.row.col.f32.bf16.bf16.f32 "
        "{%0,%1,%2,%3}, {%4,%5,%6,%7}, {%8,%9}, {%0,%1,%2,%3};"
        : "+f"(d[0]), "+f"(d[1]), "+f"(d[2]), "+f"(d[3])
        : "r"(a[0]), "r"(a[1]), "r"(a[2]), "r"(a[3]), "r"(b[0]), "r"(b[1]));
}

#define LDSM_X4(r0, r1, r2, r3, addr) \
    asm volatile("ldmatrix.sync.aligned.m8n8.x4.shared.b16 {%0,%1,%2,%3}, [%4];" \
                 : "=r"(r0), "=r"(r1), "=r"(r2), "=r"(r3) : "r"(addr))

__device__ __forceinline__ uint32_t bf2u(__nv_bfloat162 v) {
    return *reinterpret_cast<uint32_t*>(&v);
}

__device__ __forceinline__ void split4(float4 v, uint2& h, uint2& l) {
    __nv_bfloat162 H0 = __floats2bfloat162_rn(v.x, v.y);
    __nv_bfloat162 H1 = __floats2bfloat162_rn(v.z, v.w);
    float2 f0 = __bfloat1622float2(H0);
    float2 f1 = __bfloat1622float2(H1);
    __nv_bfloat162 L0 = __floats2bfloat162_rn(v.x - f0.x, v.y - f0.y);
    __nv_bfloat162 L1 = __floats2bfloat162_rn(v.z - f1.x, v.w - f1.y);
    h = make_uint2(bf2u(H0), bf2u(H1));
    l = make_uint2(bf2u(L0), bf2u(L1));
}

// ---------------------------------------------------------------------------
// lambda[h]
// ---------------------------------------------------------------------------
__global__ void lambda_kernel(const float* __restrict__ lq1, const float* __restrict__ lk1,
                              const float* __restrict__ lq2, const float* __restrict__ lk2) {
    int w = threadIdx.x >> 5, lane = threadIdx.x & 31;
    int base = w * 64;
    float s1 = lq1[base+lane]*lk1[base+lane] + lq1[base+32+lane]*lk1[base+32+lane];
    float s2 = lq2[base+lane]*lk2[base+lane] + lq2[base+32+lane]*lk2[base+32+lane];
    #pragma unroll
    for (int off = 16; off; off >>= 1) {
        s1 += __shfl_xor_sync(0xffffffffu, s1, off);
        s2 += __shfl_xor_sync(0xffffffffu, s2, off);
    }
    if (lane == 0) g_lam[w] = expf(s1) - expf(s2) + 0.8f;
}

// ---------------------------------------------------------------------------
// tf32 tensor-core GEMM (R5 structure) + ldmatrix fragment loads.
// C[M,N] = A[M,K] @ W[N,K]^T (NT). 128x128x32 tile, 8 warps of 64(M)x32(N).
// A-frag: one ldmatrix.x4 per m16 tile (matrices = {m0-7,kc},{m8-15,kc},
// {m0-7,kc+4},{m8-15,kc+4} -> af[0..3] exactly). B-frag: one x4 per 2 n-tiles.
// MODE 0: C row-major (ld=DMODEL). MODE 1: fused QKV scatter.
// ---------------------------------------------------------------------------
template<int MODE>
__global__ __launch_bounds__(256, 2) void gemm_tf32(
    const float* __restrict__ A,
    const float* __restrict__ B0, const float* __restrict__ B1, const float* __restrict__ B2,
    float* __restrict__ C0, float* __restrict__ C1, float* __restrict__ C2,
    int K)
{
    __shared__ __align__(16) float As[128][GP];
    __shared__ __align__(16) float Bs[128][GP];

    int t = threadIdx.x;
    int wid = t >> 5, lane = t & 31;
    int row0 = blockIdx.y * 128;

    const float* Bm;
    float* C;
    int col0;
    if (MODE == 1) {
        int which = blockIdx.x >> 4;
        col0 = (blockIdx.x & 15) * 128;
        Bm = (which == 0) ? B0 : ((which == 1) ? B1 : B2);
        C  = (which == 0) ? C0 : ((which == 1) ? C1 : C2);
    } else {
        col0 = blockIdx.x * 128;
        Bm = B0; C = C0;
    }

    int r0 = t >> 3;
    int kq = (t & 7) * 4;
    const float* Ag = A  + (size_t)(row0 + r0) * K + kq;
    const float* Bg = Bm + (size_t)(col0 + r0) * K + kq;

    float4 ar[4], br[4];
    #pragma unroll
    for (int l = 0; l < 4; l++) {
        ar[l] = *(const float4*)(Ag + (size_t)l * 32 * K);
        br[l] = *(const float4*)(Bg + (size_t)l * 32 * K);
    }

    float acc[4][4][4];
    #pragma unroll
    for (int i = 0; i < 4; i++)
        #pragma unroll
        for (int j = 0; j < 4; j++)
            #pragma unroll
            for (int r = 0; r < 4; r++) acc[i][j][r] = 0.f;

    int wm = (wid & 1) * 64;
    int wn = (wid >> 1) * 32;
    int fr = lane >> 2;
    int fc = lane & 3;

    // ldmatrix per-lane base addresses
    int row_off = lane & 7, sel = lane >> 3;
    // A: matrices {(m+0,kc),(m+8,kc),(m+0,kc+4),(m+8,kc+4)}
    uint32_t aA = (uint32_t)__cvta_generic_to_shared(
        &As[wm + (sel & 1) * 8 + row_off][(sel >> 1) * 4]);
    // B: matrices {(n+0,kc),(n+0,kc+4),(n+8,kc),(n+8,kc+4)} -> {bf[j][0],bf[j][1],bf[j+1][0],bf[j+1][1]}
    uint32_t aB = (uint32_t)__cvta_generic_to_shared(
        &Bs[wn + (sel >> 1) * 8 + row_off][(sel & 1) * 4]);

    for (int k0 = 0; k0 < K; k0 += 32) {
        #pragma unroll
        for (int l = 0; l < 4; l++) {
            uint4 ua = make_uint4(f2tf(ar[l].x), f2tf(ar[l].y), f2tf(ar[l].z), f2tf(ar[l].w));
            *(uint4*)&As[r0 + l*32][kq] = ua;
            uint4 ub = make_uint4(f2tf(br[l].x), f2tf(br[l].y), f2tf(br[l].z), f2tf(br[l].w));
            *(uint4*)&Bs[r0 + l*32][kq] = ub;
        }
        __syncthreads();

        if (k0 + 32 < K) {
            #pragma unroll
            for (int l = 0; l < 4; l++) {
                ar[l] = *(const float4*)(Ag + (size_t)l * 32 * K + k0 + 32);
                br[l] = *(const float4*)(Bg + (size_t)l * 32 * K + k0 + 32);
            }
        }

        #pragma unroll
        for (int kc = 0; kc < 32; kc += 8) {
            uint32_t af[4][4], bfr[8];
            #pragma unroll
            for (int i = 0; i < 4; i++) {
                uint32_t ad = aA + (uint32_t)((i * 16 * GP + kc) * 4);
                LDSM_X4(af[i][0], af[i][1], af[i][2], af[i][3], ad);
            }
            #pragma unroll
            for (int jp = 0; jp < 2; jp++) {
                uint32_t bd = aB + (uint32_t)((jp * 16 * GP + kc) * 4);
                LDSM_X4(bfr[jp*4+0], bfr[jp*4+1], bfr[jp*4+2], bfr[jp*4+3], bd);
            }
            #pragma unroll
            for (int i = 0; i < 4; i++)
                #pragma unroll
                for (int j = 0; j < 4; j++)
                    mma_tf32(acc[i][j], af[i], &bfr[j*2]);
        }
        __syncthreads();
    }

    #pragma unroll
    for (int i = 0; i < 4; i++) {
        int rr = row0 + wm + i*16 + fr;
        #pragma unroll
        for (int j = 0; j < 4; j++) {
            int cc = col0 + wn + j*8 + fc*2;
            float2 v0 = make_float2(acc[i][j][0], acc[i][j][1]);
            float2 v1 = make_float2(acc[i][j][2], acc[i][j][3]);
            if (MODE == 0) {
                *(float2*)(C + (size_t)rr * DMODEL + cc) = v0;
                *(float2*)(C + (size_t)(rr + 8) * DMODEL + cc) = v1;
            } else {
                int h = cc >> 7, e = cc & 127;
                int bb = rr >> 10, n = rr & 1023;
                *(float2*)(C + (((size_t)(bb*NUM_HEADS + h) * NN + n) * DE + e)) = v0;
                int rr2 = rr + 8;
                bb = rr2 >> 10; n = rr2 & 1023;
                *(float2*)(C + (((size_t)(bb*NUM_HEADS + h) * NN + n) * DE + e)) = v1;
            }
        }
    }
}

// ---------------------------------------------------------------------------
// Dual-stream flash attention (R9-proven config, unchanged):
// bf16 hi/lo logits, V overlaying K via cp.async, tf32 PV, deferred l, LPT.
// ---------------------------------------------------------------------------
__global__ __launch_bounds__(256, 2) void attn_kernel(const float* __restrict__ rms_scale) {
    extern __shared__ float sm[];
    uint32_t* Qh = (uint32_t*)sm;              // 64 x WQK words
    uint32_t* Ql = Qh + 64*WQK;
    uint32_t* Kh = Ql + 64*WQK;                // union with V
    uint32_t* Kl = Kh + 64*WQK;
    float*    Vs = (float*)Kh;                 // 64 x VP raw fp32
    float*    P1 = (float*)(Kl + 64*WQK);      // 64 x PP tf32
    float*    P2 = P1 + 64*PP;
    float*   bm1 = P2 + 64*PP;
    float*   bm2 = bm1 + 128;
    float*   bs1 = bm2 + 128;
    float*   bs2 = bs1 + 128;

    int t  = threadIdx.x;
    int bh = blockIdx.y;
    int h  = bh & (NUM_HEADS - 1);
    int b  = bh >> 4;
    int qi = gridDim.x - 1 - blockIdx.x;   // LPT
    int qb = qi * 64;
    const float* Qp = g_Q + (size_t)bh * NN * DE;
    const float* Kp = g_K + (size_t)bh * NN * DE;
    const float* Vp = g_V + (size_t)bh * NN * DE;

    int lane = t & 31, wid = t >> 5;
    int gid = lane >> 2, tig = lane & 3;
    int rt = (wid >> 1) * 16;
    int half = wid & 1;
    int ch = half * 32;
    int nh = half * 64;
    int rA = rt + gid, rB = rt + gid + 8;

    uint32_t vsm0 = (uint32_t)__cvta_generic_to_shared(Vs);

    #pragma unroll
    for (int l = 0; l < 8; l++) {
        int c = t + l*256;
        int r = c >> 5, dq = (c & 31) * 4;
        float4 q = *(const float4*)(Qp + (size_t)(qb + r)*DE + dq);
        uint2 hw, lw;
        split4(q, hw, lw);
        int wi = r*WQK + (dq >> 1);
        *(uint2*)&Qh[wi] = hw;
        *(uint2*)&Ql[wi] = lw;
    }

    float m1a = -1e30f, m1b = -1e30f, m2a = -1e30f, m2b = -1e30f;
    float l1a = 0.f, l1b = 0.f, l2a = 0.f, l2b = 0.f;
    float o1[8][4], o2[8][4];
    #pragma unroll
    for (int f = 0; f < 8; f++)
        #pragma unroll
        for (int r = 0; r < 4; r++) { o1[f][r] = 0.f; o2[f][r] = 0.f; }

    float lam = g_lam[h];

    int nkb = qi + 1;
    for (int jb = 0; jb < nkb; jb++) {
        int kb = jb * 64;

        #pragma unroll
        for (int l = 0; l < 8; l++) {
            int c = t + l*256;
            int r = c >> 5, dq = (c & 31) * 4;
            float4 kq = *(const float4*)(Kp + (size_t)(kb + r)*DE + dq);
            uint2 hw, lw;
            split4(kq, hw, lw);
            int wi = r*WQK + (dq >> 1);
            *(uint2*)&Kh[wi] = hw;
            *(uint2*)&Kl[wi] = lw;
        }
        __syncthreads();

        float s1[4][4], s2[4][4];
        #pragma unroll
        for (int i = 0; i < 4; i++)
            #pragma unroll
            for (int j = 0; j < 4; j++) { s1[i][j] = 0.f; s2[i][j] = 0.f; }

        #pragma unroll
        for (int kcw = 0; kcw < 4; kcw++) {
            int wb1 = kcw * 8;
            int wb2 = 32 + kcw * 8;
            uint32_t ah[4], al[4];
            ah[0] = Qh[rA*WQK + wb1 + tig];     ah[1] = Qh[rB*WQK + wb1 + tig];
            ah[2] = Qh[rA*WQK + wb1 + 4 + tig]; ah[3] = Qh[rB*WQK + wb1 + 4 + tig];
            al[0] = Ql[rA*WQK + wb1 + tig];     al[1] = Ql[rB*WQK + wb1 + tig];
            al[2] = Ql[rA*WQK + wb1 + 4 + tig]; al[3] = Ql[rB*WQK + wb1 + 4 + tig];
            #pragma unroll
            for (int nt = 0; nt < 4; nt++) {
                int n0 = ch + nt*8 + gid;
                uint32_t bhf[2], blf[2];
                bhf[0] = Kh[n0*WQK + wb1 + tig];
                bhf[1] = Kh[n0*WQK + wb1 + 4 + tig];
                blf[0] = Kl[n0*WQK + wb1 + tig];
                blf[1] = Kl[n0*WQK + wb1 + 4 + tig];
                mma_bf16(s1[nt], ah, bhf);
                mma_bf16(s1[nt], al, bhf);
                mma_bf16(s1[nt], ah, blf);
            }
            ah[0] = Qh[rA*WQK + wb2 + tig];     ah[1] = Qh[rB*WQK + wb2 + tig];
            ah[2] = Qh[rA*WQK + wb2 + 4 + tig]; ah[3] = Qh[rB*WQK + wb2 + 4 + tig];
            al[0] = Ql[rA*WQK + wb2 + tig];     al[1] = Ql[rB*WQK + wb2 + tig];
            al[2] = Ql[rA*WQK + wb2 + 4 + tig]; al[3] = Ql[rB*WQK + wb2 + 4 + tig];
            #pragma unroll
            for (int nt = 0; nt < 4; nt++) {
                int n0 = ch + nt*8 + gid;
                uint32_t bhf[2], blf[2];
                bhf[0] = Kh[n0*WQK + wb2 + tig];
                bhf[1] = Kh[n0*WQK + wb2 + 4 + tig];
                blf[0] = Kl[n0*WQK + wb2 + tig];
                blf[1] = Kl[n0*WQK + wb2 + 4 + tig];
                mma_bf16(s2[nt], ah, bhf);
                mma_bf16(s2[nt], al, bhf);
                mma_bf16(s2[nt], ah, blf);
            }
        }

        bool last = (jb == nkb - 1);
        #pragma unroll
        for (int nt = 0; nt < 4; nt++)
            #pragma unroll
            for (int c = 0; c < 4; c++) {
                float v1 = s1[nt][c] * 0.125f;
                float v2 = s2[nt][c] * 0.125f;
                if (last) {
                    int col = ch + nt*8 + 2*tig + (c & 1);
                    int row = rt + gid + ((c & 2) ? 8 : 0);
                    if (col > row) { v1 = -1e30f; v2 = -1e30f; }
                }
                s1[nt][c] = v1; s2[nt][c] = v2;
            }

        float mt1a = -1e30f, mt1b = -1e30f, mt2a = -1e30f, mt2b = -1e30f;
        #pragma unroll
        for (int nt = 0; nt < 4; nt++) {
            mt1a = fmaxf(mt1a, fmaxf(s1[nt][0], s1[nt][1]));
            mt1b = fmaxf(mt1b, fmaxf(s1[nt][2], s1[nt][3]));
            mt2a = fmaxf(mt2a, fmaxf(s2[nt][0], s2[nt][1]));
            mt2b = fmaxf(mt2b, fmaxf(s2[nt][2], s2[nt][3]));
        }
        #pragma unroll
        for (int off = 1; off <= 2; off <<= 1) {
            mt1a = fmaxf(mt1a, __shfl_xor_sync(0xffffffffu, mt1a, off));
            mt1b = fmaxf(mt1b, __shfl_xor_sync(0xffffffffu, mt1b, off));
            mt2a = fmaxf(mt2a, __shfl_xor_sync(0xffffffffu, mt2a, off));
            mt2b = fmaxf(mt2b, __shfl_xor_sync(0xffffffffu, mt2b, off));
        }
        if (tig == 0) {
            bm1[half*64 + rA] = mt1a; bm1[half*64 + rB] = mt1b;
            bm2[half*64 + rA] = mt2a; bm2[half*64 + rB] = mt2b;
        }
        __syncthreads();

        #pragma unroll
        for (int l = 0; l < 8; l++) {
            int c = t + l*256;
            int r = c >> 5, dq = (c & 31) * 4;
            uint32_t dst = vsm0 + (uint32_t)((r*VP + dq) * 4);
            const float* src = Vp + (size_t)(kb + r)*DE + dq;
            asm volatile("cp.async.cg.shared.global [%0], [%1], 16;" :: "r"(dst), "l"(src));
        }
        asm volatile("cp.async.commit_group;" ::: "memory");

        float M1a = fmaxf(m1a, fmaxf(bm1[rA], bm1[64 + rA]));
        float M1b = fmaxf(m1b, fmaxf(bm1[rB], bm1[64 + rB]));
        float M2a = fmaxf(m2a, fmaxf(bm2[rA], bm2[64 + rA]));
        float M2b = fmaxf(m2b, fmaxf(bm2[rB], bm2[64 + rB]));
        float c1a = __expf(m1a - M1a), c1b = __expf(m1b - M1b);
        float c2a = __expf(m2a - M2a), c2b = __expf(m2b - M2b);
        m1a = M1a; m1b = M1b; m2a = M2a; m2b = M2b;

        float ps1a = 0.f, ps1b = 0.f, ps2a = 0.f, ps2b = 0.f;
        #pragma unroll
        for (int nt = 0; nt < 4; nt++) {
            int colb = ch + nt*8 + 2*tig;
            float p0 = __uint_as_float(f2tf(__expf(s1[nt][0] - M1a)));
            float p1 = __uint_as_float(f2tf(__expf(s1[nt][1] - M1a)));
            float p2 = __uint_as_float(f2tf(__expf(s1[nt][2] - M1b)));
            float p3 = __uint_as_float(f2tf(__expf(s1[nt][3] - M1b)));
            ps1a += p0 + p1; ps1b += p2 + p3;
            *(float2*)&P1[rA*PP + colb] = make_float2(p0, p1);
            *(float2*)&P1[rB*PP + colb] = make_float2(p2, p3);
            float q0 = __uint_as_float(f2tf(__expf(s2[nt][0] - M2a)));
            float q1 = __uint_as_float(f2tf(__expf(s2[nt][1] - M2a)));
            float q2 = __uint_as_float(f2tf(__expf(s2[nt][2] - M2b)));
            float q3 = __uint_as_float(f2tf(__expf(s2[nt][3] - M2b)));
            ps2a += q0 + q1; ps2b += q2 + q3;
            *(float2*)&P2[rA*PP + colb] = make_float2(q0, q1);
            *(float2*)&P2[rB*PP + colb] = make_float2(q2, q3);
        }
        l1a = l1a*c1a + ps1a;
        l1b = l1b*c1b + ps1b;
        l2a = l2a*c2a + ps2a;
        l2b = l2b*c2b + ps2b;

        asm volatile("cp.async.wait_group 0;" ::: "memory");
        __syncthreads();

        #pragma unroll
        for (int f = 0; f < 8; f++) {
            o1[f][0] *= c1a; o1[f][1] *= c1a; o1[f][2] *= c1b; o1[f][3] *= c1b;
            o2[f][0] *= c2a; o2[f][1] *= c2a; o2[f][2] *= c2b; o2[f][3] *= c2b;
        }
        #pragma unroll
        for (int kc = 0; kc < 64; kc += 8) {
            uint32_t a1f[4], a2f[4];
            a1f[0] = __float_as_uint(P1[rA*PP + kc + tig]);
            a1f[1] = __float_as_uint(P1[rB*PP + kc + tig]);
            a1f[2] = __float_as_uint(P1[rA*PP + kc + tig + 4]);
            a1f[3] = __float_as_uint(P1[rB*PP + kc + tig + 4]);
            a2f[0] = __float_as_uint(P2[rA*PP + kc + tig]);
            a2f[1] = __float_as_uint(P2[rB*PP + kc + tig]);
            a2f[2] = __float_as_uint(P2[rA*PP + kc + tig + 4]);
            a2f[3] = __float_as_uint(P2[rB*PP + kc + tig + 4]);
            #pragma unroll
            for (int f = 0; f < 8; f++) {
                uint32_t bf[2];
                bf[0] = f2tf(Vs[(kc + tig    )*VP + nh + f*8 + gid]);
                bf[1] = f2tf(Vs[(kc + tig + 4)*VP + nh + f*8 + gid]);
                mma_tf32(o1[f], a1f, bf);
                mma_tf32(o2[f], a2f, bf);
            }
        }
        __syncthreads();
    }

    #pragma unroll
    for (int off = 1; off <= 2; off <<= 1) {
        l1a += __shfl_xor_sync(0xffffffffu, l1a, off);
        l1b += __shfl_xor_sync(0xffffffffu, l1b, off);
        l2a += __shfl_xor_sync(0xffffffffu, l2a, off);
        l2b += __shfl_xor_sync(0xffffffffu, l2b, off);
    }
    if (tig == 0) {
        bs1[half*64 + rA] = l1a; bs1[half*64 + rB] = l1b;
        bs2[half*64 + rA] = l2a; bs2[half*64 + rB] = l2b;
    }
    __syncthreads();
    float il1a = 1.0f / (bs1[rA] + bs1[64 + rA]);
    float il1b = 1.0f / (bs1[rB] + bs1[64 + rB]);
    float il2a = 1.0f / (bs2[rA] + bs2[64 + rA]);
    float il2b = 1.0f / (bs2[rB] + bs2[64 + rB]);

    float ssA = 0.f, ssB = 0.f;
    #pragma unroll
    for (int f = 0; f < 8; f++) {
        o1[f][0] = o1[f][0]*il1a - lam*o2[f][0]*il2a;
        o1[f][1] = o1[f][1]*il1a - lam*o2[f][1]*il2a;
        o1[f][2] = o1[f][2]*il1b - lam*o2[f][2]*il2b;
        o1[f][3] = o1[f][3]*il1b - lam*o2[f][3]*il2b;
        ssA += o1[f][0]*o1[f][0] + o1[f][1]*o1[f][1];
        ssB += o1[f][2]*o1[f][2] + o1[f][3]*o1[f][3];
    }
    ssA += __shfl_xor_sync(0xffffffffu, ssA, 1);
    ssA += __shfl_xor_sync(0xffffffffu, ssA, 2);
    ssB += __shfl_xor_sync(0xffffffffu, ssB, 1);
    ssB += __shfl_xor_sync(0xffffffffu, ssB, 2);

    if (tig == 0) {
        float* dst = half ? bm2 : bm1;
        dst[rA] = ssA;
        dst[rB] = ssB;
    }
    __syncthreads();
    float totA = bm1[rA] + bm2[rA];
    float totB = bm1[rB] + bm2[rB];
    float scA = rsqrtf(totA * (1.0f/128.0f) + 1e-5f) * 0.2f;
    float scB = rsqrtf(totB * (1.0f/128.0f) + 1e-5f) * 0.2f;

    size_t obaseA = ((size_t)b * NN + qb + rA) * D2 + h * DE;
    size_t obaseB = ((size_t)b * NN + qb + rB) * D2 + h * DE;
    #pragma unroll
    for (int f = 0; f < 8; f++) {
        int col = nh + f*8 + 2*tig;
        float2 rs = *(const float2*)(rms_scale + col);
        *(float2*)(g_Oc + obaseA + col) = make_float2(o1[f][0]*scA*rs.x, o1[f][1]*scA*rs.y);
        *(float2*)(g_Oc + obaseB + col) = make_float2(o1[f][2]*scB*rs.x, o1[f][3]*scB*rs.y);
    }
}

#define ATTN_SMEM (26624 * 4)   // 106496 bytes -> 2 blocks/SM

extern "C" void kernel_launch(void* const* d_in, const int* in_sizes, int n_in,
                              void* d_out, int out_size) {
    const float* X   = (const float*)d_in[0];
    const float* Wq  = (const float*)d_in[1];
    const float* Wk  = (const float*)d_in[2];
    const float* Wv  = (const float*)d_in[3];
    const float* Wo  = (const float*)d_in[4];
    const float* lq1 = (const float*)d_in[5];
    const float* lk1 = (const float*)d_in[6];
    const float* lq2 = (const float*)d_in[7];
    const float* lk2 = (const float*)d_in[8];
    const float* rms = (const float*)d_in[9];

    float *pQ, *pK, *pV, *pOc;
    cudaGetSymbolAddress((void**)&pQ,  g_Q);
    cudaGetSymbolAddress((void**)&pK,  g_K);
    cudaGetSymbolAddress((void**)&pV,  g_V);
    cudaGetSymbolAddress((void**)&pOc, g_Oc);

    lambda_kernel<<<1, 512>>>(lq1, lk1, lq2, lk2);

    dim3 gqkv(48, MTOT/128);
    gemm_tf32<1><<<gqkv, 256>>>(X, Wq, Wk, Wv, pQ, pK, pV, DMODEL);

    cudaFuncSetAttribute(attn_kernel, cudaFuncAttributeMaxDynamicSharedMemorySize, ATTN_SMEM);
    attn_kernel<<<dim3(NN/64, BB*NUM_HEADS), 256, ATTN_SMEM>>>(rms);

    dim3 gout(DMODEL/128, MTOT/128);
    gemm_tf32<0><<<gout, 256>>>(pOc, Wo, nullptr, nullptr, (float*)d_out, nullptr, nullptr, D2);
}

// round 16
// speedup vs baseline: 1.1304x; 1.0495x over previous
#include <cuda_runtime.h>
#include <cuda_bf16.h>
#include <math.h>
#include <stdint.h>

#define NUM_HEADS 16
#define DHEAD 64
#define DE 128          // 2*DHEAD per head
#define DMODEL 1024
#define D2 2048
#define BB 4
#define NN 1024
#define MTOT (BB*NN)    // 4096
#define GP 36           // GEMM smem pitch (144B rows -> ldmatrix conflict-free)
#define SSTG (128*GP)   // floats per GEMM stage per operand
#define WQK 68          // word pitch for bf16x2 Q/K arrays (attention)
#define VP  136         // float pitch for raw V tile (attention)
#define PP  68          // float pitch for P tiles (attention)

// Scratch (device globals; allocation APIs are forbidden)
__device__ float g_Q[(size_t)BB*NUM_HEADS*NN*DE];
__device__ float g_K[(size_t)BB*NUM_HEADS*NN*DE];
__device__ float g_V[(size_t)BB*NUM_HEADS*NN*DE];
__device__ float g_Oc[(size_t)BB*NN*D2];
__device__ float g_lam[NUM_HEADS];
// tf32-preconverted GEMM operands
__device__ float g_Xt[(size_t)MTOT*DMODEL];
__device__ float g_Wqt[(size_t)D2*DMODEL];
__device__ float g_Wkt[(size_t)D2*DMODEL];
__device__ float g_Wvt[(size_t)D2*DMODEL];
__device__ float g_Wot[(size_t)DMODEL*D2];

__device__ __forceinline__ uint32_t f2tf(float f) {
    uint32_t u;
    asm("cvt.rna.tf32.f32 %0, %1;" : "=r"(u) : "f"(f));
    return u;
}

__device__ __forceinline__ void mma_tf32(float* d, const uint32_t* a, const uint32_t* b) {
    asm volatile(
        "mma.sync.aligned.m16n8k8.row.col.f32.tf32.tf32.f32 "
        "{%0,%1,%2,%3}, {%4,%5,%6,%7}, {%8,%9}, {%0,%1,%2,%3};"
        : "+f"(d[0]), "+f"(d[1]), "+f"(d[2]), "+f"(d[3])
        : "r"(a[0]), "r"(a[1]), "r"(a[2]), "r"(a[3]), "r"(b[0]), "r"(b[1]));
}

__device__ __forceinline__ void mma_bf16(float* d, const uint32_t* a, const uint32_t* b) {
    asm volatile(
        "mma.sync.aligned.m16n8k16.row.col.f32.bf16.bf16.f32 "
        "{%0,%1,%2,%3}, {%4,%5,%6,%7}, {%8,%9}, {%0,%1,%2,%3};"
        : "+f"(d[0]), "+f"(d[1]), "+f"(d[2]), "+f"(d[3])
        : "r"(a[0]), "r"(a[1]), "r"(a[2]), "r"(a[3]), "r"(b[0]), "r"(b[1]));
}

#define LDSM_X4(r0, r1, r2, r3, addr) \
    asm volatile("ldmatrix.sync.aligned.m8n8.x4.shared.b16 {%0,%1,%2,%3}, [%4];" \
                 : "=r"(r0), "=r"(r1), "=r"(r2), "=r"(r3) : "r"(addr))

__device__ __forceinline__ uint32_t bf2u(__nv_bfloat162 v) {
    return *reinterpret_cast<uint32_t*>(&v);
}

__device__ __forceinline__ void split4(float4 v, uint2& h, uint2& l) {
    __nv_bfloat162 H0 = __floats2bfloat162_rn(v.x, v.y);
    __nv_bfloat162 H1 = __floats2bfloat162_rn(v.z, v.w);
    float2 f0 = __bfloat1622float2(H0);
    float2 f1 = __bfloat1622float2(H1);
    __nv_bfloat162 L0 = __floats2bfloat162_rn(v.x - f0.x, v.y - f0.y);
    __nv_bfloat162 L1 = __floats2bfloat162_rn(v.z - f1.x, v.w - f1.y);
    h = make_uint2(bf2u(H0), bf2u(H1));
    l = make_uint2(bf2u(L0), bf2u(L1));
}

// ---------------------------------------------------------------------------
// elementwise tf32 pre-convert (RNA), float4 vectorized
// ---------------------------------------------------------------------------
__global__ void cvt_tf32_kernel(const float* __restrict__ in, float* __restrict__ out, int n4) {
    int i = blockIdx.x * blockDim.x + threadIdx.x;
    int stride = gridDim.x * blockDim.x;
    for (; i < n4; i += stride) {
        float4 v = ((const float4*)in)[i];
        uint4 u = make_uint4(f2tf(v.x), f2tf(v.y), f2tf(v.z), f2tf(v.w));
        ((uint4*)out)[i] = u;
    }
}

// ---------------------------------------------------------------------------
// lambda[h]
// ---------------------------------------------------------------------------
__global__ void lambda_kernel(const float* __restrict__ lq1, const float* __restrict__ lk1,
                              const float* __restrict__ lq2, const float* __restrict__ lk2) {
    int w = threadIdx.x >> 5, lane = threadIdx.x & 31;
    int base = w * 64;
    float s1 = lq1[base+lane]*lk1[base+lane] + lq1[base+32+lane]*lk1[base+32+lane];
    float s2 = lq2[base+lane]*lk2[base+lane] + lq2[base+32+lane]*lk2[base+32+lane];
    #pragma unroll
    for (int off = 16; off; off >>= 1) {
        s1 += __shfl_xor_sync(0xffffffffu, s1, off);
        s2 += __shfl_xor_sync(0xffffffffu, s2, off);
    }
    if (lane == 0) g_lam[w] = expf(s1) - expf(s2) + 0.8f;
}

// ---------------------------------------------------------------------------
// tf32 GEMM on PRE-CONVERTED operands: cp.async double-buffered staging
// (no cvt, no STS, no prefetch regs in the hot loop) + ldmatrix fragments.
// C[M,N] = A[M,K] @ W[N,K]^T (NT). 128x128x32 tile, 8 warps of 64x32.
// ONE barrier per k-iter. MODE 0: row-major C. MODE 1: QKV scatter.
// ---------------------------------------------------------------------------
template<int MODE>
__global__ __launch_bounds__(256, 2) void gemm_tf32(
    const float* __restrict__ A,
    const float* __restrict__ B0, const float* __restrict__ B1, const float* __restrict__ B2,
    float* __restrict__ C0, float* __restrict__ C1, float* __restrict__ C2,
    int K)
{
    extern __shared__ float gsm[];
    float* As = gsm;              // [2][SSTG]
    float* Bs = gsm + 2*SSTG;     // [2][SSTG]

    int t = threadIdx.x;
    int wid = t >> 5, lane = t & 31;
    int row0 = blockIdx.y * 128;

    const float* Bm;
    float* C;
    int col0;
    if (MODE == 1) {
        int which = blockIdx.x >> 4;
        col0 = (blockIdx.x & 15) * 128;
        Bm = (which == 0) ? B0 : ((which == 1) ? B1 : B2);
        C  = (which == 0) ? C0 : ((which == 1) ? C1 : C2);
    } else {
        col0 = blockIdx.x * 128;
        Bm = B0; C = C0;
    }

    uint32_t a_s0 = (uint32_t)__cvta_generic_to_shared(As);
    uint32_t b_s0 = (uint32_t)__cvta_generic_to_shared(Bs);

    // issue one 128x32 stage for both operands: 16B cp.async, 8 per thread
    auto issue = [&](int s, int k0) {
        #pragma unroll
        for (int l = 0; l < 4; l++) {
            int idx = t + l*256;
            int r = idx >> 3, fq = (idx & 7) * 4;
            uint32_t da = a_s0 + (uint32_t)((s*SSTG + r*GP + fq) * 4);
            const float* sa = A + (size_t)(row0 + r) * K + k0 + fq;
            asm volatile("cp.async.cg.shared.global [%0], [%1], 16;" :: "r"(da), "l"(sa));
            uint32_t db = b_s0 + (uint32_t)((s*SSTG + r*GP + fq) * 4);
            const float* sb = Bm + (size_t)(col0 + r) * K + k0 + fq;
            asm volatile("cp.async.cg.shared.global [%0], [%1], 16;" :: "r"(db), "l"(sb));
        }
        asm volatile("cp.async.commit_group;" ::: "memory");
    };

    float acc[4][4][4];
    #pragma unroll
    for (int i = 0; i < 4; i++)
        #pragma unroll
        for (int j = 0; j < 4; j++)
            #pragma unroll
            for (int r = 0; r < 4; r++) acc[i][j][r] = 0.f;

    int wm = (wid & 1) * 64;
    int wn = (wid >> 1) * 32;
    int fr = lane >> 2;
    int fc = lane & 3;

    // ldmatrix per-lane base addresses (stage 0; add s*SSTG*4 per stage)
    int row_off = lane & 7, sel = lane >> 3;
    uint32_t aA0 = a_s0 + (uint32_t)(((wm + (sel & 1) * 8 + row_off) * GP + (sel >> 1) * 4) * 4);
    uint32_t aB0 = b_s0 + (uint32_t)(((wn + (sel >> 1) * 8 + row_off) * GP + (sel & 1) * 4) * 4);

    issue(0, 0);

    for (int k0 = 0; k0 < K; k0 += 32) {
        int s = (k0 >> 5) & 1;
        bool more = (k0 + 32 < K);

        asm volatile("cp.async.wait_group 0;" ::: "memory");
        __syncthreads();                 // stage s visible; prior reads of s^1 done
        if (more) issue(s ^ 1, k0 + 32); // overlaps the mma below

        uint32_t aA = aA0 + (uint32_t)(s * SSTG * 4);
        uint32_t aB = aB0 + (uint32_t)(s * SSTG * 4);
        #pragma unroll
        for (int kc = 0; kc < 32; kc += 8) {
            uint32_t af[4][4], bfr[8];
            #pragma unroll
            for (int i = 0; i < 4; i++) {
                uint32_t ad = aA + (uint32_t)((i * 16 * GP + kc) * 4);
                LDSM_X4(af[i][0], af[i][1], af[i][2], af[i][3], ad);
            }
            #pragma unroll
            for (int jp = 0; jp < 2; jp++) {
                uint32_t bd = aB + (uint32_t)((jp * 16 * GP + kc) * 4);
                LDSM_X4(bfr[jp*4+0], bfr[jp*4+1], bfr[jp*4+2], bfr[jp*4+3], bd);
            }
            #pragma unroll
            for (int i = 0; i < 4; i++)
                #pragma unroll
                for (int j = 0; j < 4; j++)
                    mma_tf32(acc[i][j], af[i], &bfr[j*2]);
        }
    }

    #pragma unroll
    for (int i = 0; i < 4; i++) {
        int rr = row0 + wm + i*16 + fr;
        #pragma unroll
        for (int j = 0; j < 4; j++) {
            int cc = col0 + wn + j*8 + fc*2;
            float2 v0 = make_float2(acc[i][j][0], acc[i][j][1]);
            float2 v1 = make_float2(acc[i][j][2], acc[i][j][3]);
            if (MODE == 0) {
                *(float2*)(C + (size_t)rr * DMODEL + cc) = v0;
                *(float2*)(C + (size_t)(rr + 8) * DMODEL + cc) = v1;
            } else {
                int h = cc >> 7, e = cc & 127;
                int bb = rr >> 10, n = rr & 1023;
                *(float2*)(C + (((size_t)(bb*NUM_HEADS + h) * NN + n) * DE + e)) = v0;
                int rr2 = rr + 8;
                bb = rr2 >> 10; n = rr2 & 1023;
                *(float2*)(C + (((size_t)(bb*NUM_HEADS + h) * NN + n) * DE + e)) = v1;
            }
        }
    }
}

#define GEMM_SMEM (4 * SSTG * 4)   // 73728 bytes -> 2 CTAs/SM

// ---------------------------------------------------------------------------
// Dual-stream flash attention (R9-proven config): bf16 hi/lo logits, V overlay
// via cp.async, tf32 PV, deferred l, LPT. Epilogue now writes Oc as tf32 bits
// (f2tf idempotent -> downstream GEMM values bit-identical to before).
// ---------------------------------------------------------------------------
__global__ __launch_bounds__(256, 2) void attn_kernel(const float* __restrict__ rms_scale) {
    extern __shared__ float sm[];
    uint32_t* Qh = (uint32_t*)sm;              // 64 x WQK words
    uint32_t* Ql = Qh + 64*WQK;
    uint32_t* Kh = Ql + 64*WQK;                // union with V
    uint32_t* Kl = Kh + 64*WQK;
    float*    Vs = (float*)Kh;                 // 64 x VP raw fp32
    float*    P1 = (float*)(Kl + 64*WQK);      // 64 x PP tf32
    float*    P2 = P1 + 64*PP;
    float*   bm1 = P2 + 64*PP;
    float*   bm2 = bm1 + 128;
    float*   bs1 = bm2 + 128;
    float*   bs2 = bs1 + 128;

    int t  = threadIdx.x;
    int bh = blockIdx.y;
    int h  = bh & (NUM_HEADS - 1);
    int b  = bh >> 4;
    int qi = gridDim.x - 1 - blockIdx.x;   // LPT
    int qb = qi * 64;
    const float* Qp = g_Q + (size_t)bh * NN * DE;
    const float* Kp = g_K + (size_t)bh * NN * DE;
    const float* Vp = g_V + (size_t)bh * NN * DE;

    int lane = t & 31, wid = t >> 5;
    int gid = lane >> 2, tig = lane & 3;
    int rt = (wid >> 1) * 16;
    int half = wid & 1;
    int ch = half * 32;
    int nh = half * 64;
    int rA = rt + gid, rB = rt + gid + 8;

    uint32_t vsm0 = (uint32_t)__cvta_generic_to_shared(Vs);

    #pragma unroll
    for (int l = 0; l < 8; l++) {
        int c = t + l*256;
        int r = c >> 5, dq = (c & 31) * 4;
        float4 q = *(const float4*)(Qp + (size_t)(qb + r)*DE + dq);
        uint2 hw, lw;
        split4(q, hw, lw);
        int wi = r*WQK + (dq >> 1);
        *(uint2*)&Qh[wi] = hw;
        *(uint2*)&Ql[wi] = lw;
    }

    float m1a = -1e30f, m1b = -1e30f, m2a = -1e30f, m2b = -1e30f;
    float l1a = 0.f, l1b = 0.f, l2a = 0.f, l2b = 0.f;
    float o1[8][4], o2[8][4];
    #pragma unroll
    for (int f = 0; f < 8; f++)
        #pragma unroll
        for (int r = 0; r < 4; r++) { o1[f][r] = 0.f; o2[f][r] = 0.f; }

    float lam = g_lam[h];

    int nkb = qi + 1;
    for (int jb = 0; jb < nkb; jb++) {
        int kb = jb * 64;

        #pragma unroll
        for (int l = 0; l < 8; l++) {
            int c = t + l*256;
            int r = c >> 5, dq = (c & 31) * 4;
            float4 kq = *(const float4*)(Kp + (size_t)(kb + r)*DE + dq);
            uint2 hw, lw;
            split4(kq, hw, lw);
            int wi = r*WQK + (dq >> 1);
            *(uint2*)&Kh[wi] = hw;
            *(uint2*)&Kl[wi] = lw;
        }
        __syncthreads();

        float s1[4][4], s2[4][4];
        #pragma unroll
        for (int i = 0; i < 4; i++)
            #pragma unroll
            for (int j = 0; j < 4; j++) { s1[i][j] = 0.f; s2[i][j] = 0.f; }

        #pragma unroll
        for (int kcw = 0; kcw < 4; kcw++) {
            int wb1 = kcw * 8;
            int wb2 = 32 + kcw * 8;
            uint32_t ah[4], al[4];
            ah[0] = Qh[rA*WQK + wb1 + tig];     ah[1] = Qh[rB*WQK + wb1 + tig];
            ah[2] = Qh[rA*WQK + wb1 + 4 + tig]; ah[3] = Qh[rB*WQK + wb1 + 4 + tig];
            al[0] = Ql[rA*WQK + wb1 + tig];     al[1] = Ql[rB*WQK + wb1 + tig];
            al[2] = Ql[rA*WQK + wb1 + 4 + tig]; al[3] = Ql[rB*WQK + wb1 + 4 + tig];
            #pragma unroll
            for (int nt = 0; nt < 4; nt++) {
                int n0 = ch + nt*8 + gid;
                uint32_t bhf[2], blf[2];
                bhf[0] = Kh[n0*WQK + wb1 + tig];
                bhf[1] = Kh[n0*WQK + wb1 + 4 + tig];
                blf[0] = Kl[n0*WQK + wb1 + tig];
                blf[1] = Kl[n0*WQK + wb1 + 4 + tig];
                mma_bf16(s1[nt], ah, bhf);
                mma_bf16(s1[nt], al, bhf);
                mma_bf16(s1[nt], ah, blf);
            }
            ah[0] = Qh[rA*WQK + wb2 + tig];     ah[1] = Qh[rB*WQK + wb2 + tig];
            ah[2] = Qh[rA*WQK + wb2 + 4 + tig]; ah[3] = Qh[rB*WQK + wb2 + 4 + tig];
            al[0] = Ql[rA*WQK + wb2 + tig];     al[1] = Ql[rB*WQK + wb2 + tig];
            al[2] = Ql[rA*WQK + wb2 + 4 + tig]; al[3] = Ql[rB*WQK + wb2 + 4 + tig];
            #pragma unroll
            for (int nt = 0; nt < 4; nt++) {
                int n0 = ch + nt*8 + gid;
                uint32_t bhf[2], blf[2];
                bhf[0] = Kh[n0*WQK + wb2 + tig];
                bhf[1] = Kh[n0*WQK + wb2 + 4 + tig];
                blf[0] = Kl[n0*WQK + wb2 + tig];
                blf[1] = Kl[n0*WQK + wb2 + 4 + tig];
                mma_bf16(s2[nt], ah, bhf);
                mma_bf16(s2[nt], al, bhf);
                mma_bf16(s2[nt], ah, blf);
            }
        }

        bool last = (jb == nkb - 1);
        #pragma unroll
        for (int nt = 0; nt < 4; nt++)
            #pragma unroll
            for (int c = 0; c < 4; c++) {
                float v1 = s1[nt][c] * 0.125f;
                float v2 = s2[nt][c] * 0.125f;
                if (last) {
                    int col = ch + nt*8 + 2*tig + (c & 1);
                    int row = rt + gid + ((c & 2) ? 8 : 0);
                    if (col > row) { v1 = -1e30f; v2 = -1e30f; }
                }
                s1[nt][c] = v1; s2[nt][c] = v2;
            }

        float mt1a = -1e30f, mt1b = -1e30f, mt2a = -1e30f, mt2b = -1e30f;
        #pragma unroll
        for (int nt = 0; nt < 4; nt++) {
            mt1a = fmaxf(mt1a, fmaxf(s1[nt][0], s1[nt][1]));
            mt1b = fmaxf(mt1b, fmaxf(s1[nt][2], s1[nt][3]));
            mt2a = fmaxf(mt2a, fmaxf(s2[nt][0], s2[nt][1]));
            mt2b = fmaxf(mt2b, fmaxf(s2[nt][2], s2[nt][3]));
        }
        #pragma unroll
        for (int off = 1; off <= 2; off <<= 1) {
            mt1a = fmaxf(mt1a, __shfl_xor_sync(0xffffffffu, mt1a, off));
            mt1b = fmaxf(mt1b, __shfl_xor_sync(0xffffffffu, mt1b, off));
            mt2a = fmaxf(mt2a, __shfl_xor_sync(0xffffffffu, mt2a, off));
            mt2b = fmaxf(mt2b, __shfl_xor_sync(0xffffffffu, mt2b, off));
        }
        if (tig == 0) {
            bm1[half*64 + rA] = mt1a; bm1[half*64 + rB] = mt1b;
            bm2[half*64 + rA] = mt2a; bm2[half*64 + rB] = mt2b;
        }
        __syncthreads();

        #pragma unroll
        for (int l = 0; l < 8; l++) {
            int c = t + l*256;
            int r = c >> 5, dq = (c & 31) * 4;
            uint32_t dst = vsm0 + (uint32_t)((r*VP + dq) * 4);
            const float* src = Vp + (size_t)(kb + r)*DE + dq;
            asm volatile("cp.async.cg.shared.global [%0], [%1], 16;" :: "r"(dst), "l"(src));
        }
        asm volatile("cp.async.commit_group;" ::: "memory");

        float M1a = fmaxf(m1a, fmaxf(bm1[rA], bm1[64 + rA]));
        float M1b = fmaxf(m1b, fmaxf(bm1[rB], bm1[64 + rB]));
        float M2a = fmaxf(m2a, fmaxf(bm2[rA], bm2[64 + rA]));
        float M2b = fmaxf(m2b, fmaxf(bm2[rB], bm2[64 + rB]));
        float c1a = __expf(m1a - M1a), c1b = __expf(m1b - M1b);
        float c2a = __expf(m2a - M2a), c2b = __expf(m2b - M2b);
        m1a = M1a; m1b = M1b; m2a = M2a; m2b = M2b;

        float ps1a = 0.f, ps1b = 0.f, ps2a = 0.f, ps2b = 0.f;
        #pragma unroll
        for (int nt = 0; nt < 4; nt++) {
            int colb = ch + nt*8 + 2*tig;
            float p0 = __uint_as_float(f2tf(__expf(s1[nt][0] - M1a)));
            float p1 = __uint_as_float(f2tf(__expf(s1[nt][1] - M1a)));
            float p2 = __uint_as_float(f2tf(__expf(s1[nt][2] - M1b)));
            float p3 = __uint_as_float(f2tf(__expf(s1[nt][3] - M1b)));
            ps1a += p0 + p1; ps1b += p2 + p3;
            *(float2*)&P1[rA*PP + colb] = make_float2(p0, p1);
            *(float2*)&P1[rB*PP + colb] = make_float2(p2, p3);
            float q0 = __uint_as_float(f2tf(__expf(s2[nt][0] - M2a)));
            float q1 = __uint_as_float(f2tf(__expf(s2[nt][1] - M2a)));
            float q2 = __uint_as_float(f2tf(__expf(s2[nt][2] - M2b)));
            float q3 = __uint_as_float(f2tf(__expf(s2[nt][3] - M2b)));
            ps2a += q0 + q1; ps2b += q2 + q3;
            *(float2*)&P2[rA*PP + colb] = make_float2(q0, q1);
            *(float2*)&P2[rB*PP + colb] = make_float2(q2, q3);
        }
        l1a = l1a*c1a + ps1a;
        l1b = l1b*c1b + ps1b;
        l2a = l2a*c2a + ps2a;
        l2b = l2b*c2b + ps2b;

        asm volatile("cp.async.wait_group 0;" ::: "memory");
        __syncthreads();

        #pragma unroll
        for (int f = 0; f < 8; f++) {
            o1[f][0] *= c1a; o1[f][1] *= c1a; o1[f][2] *= c1b; o1[f][3] *= c1b;
            o2[f][0] *= c2a; o2[f][1] *= c2a; o2[f][2] *= c2b; o2[f][3] *= c2b;
        }
        #pragma unroll
        for (int kc = 0; kc < 64; kc += 8) {
            uint32_t a1f[4], a2f[4];
            a1f[0] = __float_as_uint(P1[rA*PP + kc + tig]);
            a1f[1] = __float_as_uint(P1[rB*PP + kc + tig]);
            a1f[2] = __float_as_uint(P1[rA*PP + kc + tig + 4]);
            a1f[3] = __float_as_uint(P1[rB*PP + kc + tig + 4]);
            a2f[0] = __float_as_uint(P2[rA*PP + kc + tig]);
            a2f[1] = __float_as_uint(P2[rB*PP + kc + tig]);
            a2f[2] = __float_as_uint(P2[rA*PP + kc + tig + 4]);
            a2f[3] = __float_as_uint(P2[rB*PP + kc + tig + 4]);
            #pragma unroll
            for (int f = 0; f < 8; f++) {
                uint32_t bf[2];
                bf[0] = f2tf(Vs[(kc + tig    )*VP + nh + f*8 + gid]);
                bf[1] = f2tf(Vs[(kc + tig + 4)*VP + nh + f*8 + gid]);
                mma_tf32(o1[f], a1f, bf);
                mma_tf32(o2[f], a2f, bf);
            }
        }
        __syncthreads();
    }

    #pragma unroll
    for (int off = 1; off <= 2; off <<= 1) {
        l1a += __shfl_xor_sync(0xffffffffu, l1a, off);
        l1b += __shfl_xor_sync(0xffffffffu, l1b, off);
        l2a += __shfl_xor_sync(0xffffffffu, l2a, off);
        l2b += __shfl_xor_sync(0xffffffffu, l2b, off);
    }
    if (tig == 0) {
        bs1[half*64 + rA] = l1a; bs1[half*64 + rB] = l1b;
        bs2[half*64 + rA] = l2a; bs2[half*64 + rB] = l2b;
    }
    __syncthreads();
    float il1a = 1.0f / (bs1[rA] + bs1[64 + rA]);
    float il1b = 1.0f / (bs1[rB] + bs1[64 + rB]);
    float il2a = 1.0f / (bs2[rA] + bs2[64 + rA]);
    float il2b = 1.0f / (bs2[rB] + bs2[64 + rB]);

    float ssA = 0.f, ssB = 0.f;
    #pragma unroll
    for (int f = 0; f < 8; f++) {
        o1[f][0] = o1[f][0]*il1a - lam*o2[f][0]*il2a;
        o1[f][1] = o1[f][1]*il1a - lam*o2[f][1]*il2a;
        o1[f][2] = o1[f][2]*il1b - lam*o2[f][2]*il2b;
        o1[f][3] = o1[f][3]*il1b - lam*o2[f][3]*il2b;
        ssA += o1[f][0]*o1[f][0] + o1[f][1]*o1[f][1];
        ssB += o1[f][2]*o1[f][2] + o1[f][3]*o1[f][3];
    }
    ssA += __shfl_xor_sync(0xffffffffu, ssA, 1);
    ssA += __shfl_xor_sync(0xffffffffu, ssA, 2);
    ssB += __shfl_xor_sync(0xffffffffu, ssB, 1);
    ssB += __shfl_xor_sync(0xffffffffu, ssB, 2);

    if (tig == 0) {
        float* dst = half ? bm2 : bm1;
        dst[rA] = ssA;
        dst[rB] = ssB;
    }
    __syncthreads();
    float totA = bm1[rA] + bm2[rA];
    float totB = bm1[rB] + bm2[rB];
    float scA = rsqrtf(totA * (1.0f/128.0f) + 1e-5f) * 0.2f;
    float scB = rsqrtf(totB * (1.0f/128.0f) + 1e-5f) * 0.2f;

    // write Oc pre-rounded to tf32 (bit-identical to GEMM's former cvt-at-store)
    size_t obaseA = ((size_t)b * NN + qb + rA) * D2 + h * DE;
    size_t obaseB = ((size_t)b * NN + qb + rB) * D2 + h * DE;
    #pragma unroll
    for (int f = 0; f < 8; f++) {
        int col = nh + f*8 + 2*tig;
        float2 rs = *(const float2*)(rms_scale + col);
        uint2 wA = make_uint2(f2tf(o1[f][0]*scA*rs.x), f2tf(o1[f][1]*scA*rs.y));
        uint2 wB = make_uint2(f2tf(o1[f][2]*scB*rs.x), f2tf(o1[f][3]*scB*rs.y));
        *(uint2*)(g_Oc + obaseA + col) = wA;
        *(uint2*)(g_Oc + obaseB + col) = wB;
    }
}

#define ATTN_SMEM (26624 * 4)   // 106496 bytes -> 2 blocks/SM

extern "C" void kernel_launch(void* const* d_in, const int* in_sizes, int n_in,
                              void* d_out, int out_size) {
    const float* X   = (const float*)d_in[0];
    const float* Wq  = (const float*)d_in[1];
    const float* Wk  = (const float*)d_in[2];
    const float* Wv  = (const float*)d_in[3];
    const float* Wo  = (const float*)d_in[4];
    const float* lq1 = (const float*)d_in[5];
    const float* lk1 = (const float*)d_in[6];
    const float* lq2 = (const float*)d_in[7];
    const float* lk2 = (const float*)d_in[8];
    const float* rms = (const float*)d_in[9];

    float *pQ, *pK, *pV, *pOc, *pXt, *pWqt, *pWkt, *pWvt, *pWot;
    cudaGetSymbolAddress((void**)&pQ,   g_Q);
    cudaGetSymbolAddress((void**)&pK,   g_K);
    cudaGetSymbolAddress((void**)&pV,   g_V);
    cudaGetSymbolAddress((void**)&pOc,  g_Oc);
    cudaGetSymbolAddress((void**)&pXt,  g_Xt);
    cudaGetSymbolAddress((void**)&pWqt, g_Wqt);
    cudaGetSymbolAddress((void**)&pWkt, g_Wkt);
    cudaGetSymbolAddress((void**)&pWvt, g_Wvt);
    cudaGetSymbolAddress((void**)&pWot, g_Wot);

    lambda_kernel<<<1, 512>>>(lq1, lk1, lq2, lk2);

    // pre-convert GEMM operands to tf32 (idempotent; values identical to before)
    cvt_tf32_kernel<<<1184, 256>>>(X,  pXt,  MTOT*DMODEL/4);
    cvt_tf32_kernel<<<1184, 256>>>(Wq, pWqt, D2*DMODEL/4);
    cvt_tf32_kernel<<<1184, 256>>>(Wk, pWkt, D2*DMODEL/4);
    cvt_tf32_kernel<<<1184, 256>>>(Wv, pWvt, D2*DMODEL/4);
    cvt_tf32_kernel<<<1184, 256>>>(Wo, pWot, DMODEL*D2/4);

    cudaFuncSetAttribute(gemm_tf32<1>, cudaFuncAttributeMaxDynamicSharedMemorySize, GEMM_SMEM);
    cudaFuncSetAttribute(gemm_tf32<0>, cudaFuncAttributeMaxDynamicSharedMemorySize, GEMM_SMEM);

    dim3 gqkv(48, MTOT/128);
    gemm_tf32<1><<<gqkv, 256, GEMM_SMEM>>>(pXt, pWqt, pWkt, pWvt, pQ, pK, pV, DMODEL);

    cudaFuncSetAttribute(attn_kernel, cudaFuncAttributeMaxDynamicSharedMemorySize, ATTN_SMEM);
    attn_kernel<<<dim3(NN/64, BB*NUM_HEADS), 256, ATTN_SMEM>>>(rms);

    dim3 gout(DMODEL/128, MTOT/128);
    gemm_tf32<0><<<gout, 256, GEMM_SMEM>>>(pOc, pWot, nullptr, nullptr, (float*)d_out, nullptr, nullptr, D2);
}

// round 17
// speedup vs baseline: 1.1311x; 1.0007x over previous
#include <cuda_runtime.h>
#include <cuda_bf16.h>
#include <math.h>
#include <stdint.h>

#define NUM_HEADS 16
#define DHEAD 64
#define DE 128          // 2*DHEAD per head
#define DMODEL 1024
#define D2 2048
#define BB 4
#define NN 1024
#define MTOT (BB*NN)    // 4096
#define GP 36           // GEMM smem pitch (144B rows -> ldmatrix conflict-free)
#define SSTG (128*GP)   // floats per GEMM stage per operand
#define NSTG 3          // cp.async pipeline depth
#define WQK 68          // word pitch for bf16x2 Q/K arrays (attention)
#define VP  136         // float pitch for raw V tile (attention)
#define PP  68          // float pitch for P tiles (attention)

// Scratch (device globals; allocation APIs are forbidden)
__device__ float g_Q[(size_t)BB*NUM_HEADS*NN*DE];
__device__ float g_K[(size_t)BB*NUM_HEADS*NN*DE];
__device__ float g_V[(size_t)BB*NUM_HEADS*NN*DE];
__device__ float g_Oc[(size_t)BB*NN*D2];
__device__ float g_lam[NUM_HEADS];
// tf32-preconverted GEMM operands
__device__ float g_Xt[(size_t)MTOT*DMODEL];
__device__ float g_Wqt[(size_t)D2*DMODEL];
__device__ float g_Wkt[(size_t)D2*DMODEL];
__device__ float g_Wvt[(size_t)D2*DMODEL];
__device__ float g_Wot[(size_t)DMODEL*D2];

__device__ __forceinline__ uint32_t f2tf(float f) {
    uint32_t u;
    asm("cvt.rna.tf32.f32 %0, %1;" : "=r"(u) : "f"(f));
    return u;
}

__device__ __forceinline__ void mma_tf32(float* d, const uint32_t* a, const uint32_t* b) {
    asm volatile(
        "mma.sync.aligned.m16n8k8.row.col.f32.tf32.tf32.f32 "
        "{%0,%1,%2,%3}, {%4,%5,%6,%7}, {%8,%9}, {%0,%1,%2,%3};"
        : "+f"(d[0]), "+f"(d[1]), "+f"(d[2]), "+f"(d[3])
        : "r"(a[0]), "r"(a[1]), "r"(a[2]), "r"(a[3]), "r"(b[0]), "r"(b[1]));
}

__device__ __forceinline__ void mma_bf16(float* d, const uint32_t* a, const uint32_t* b) {
    asm volatile(
        "mma.sync.aligned.m16n8k16.row.col.f32.bf16.bf16.f32 "
        "{%0,%1,%2,%3}, {%4,%5,%6,%7}, {%8,%9}, {%0,%1,%2,%3};"
        : "+f"(d[0]), "+f"(d[1]), "+f"(d[2]), "+f"(d[3])
        : "r"(a[0]), "r"(a[1]), "r"(a[2]), "r"(a[3]), "r"(b[0]), "r"(b[1]));
}

#define LDSM_X4(r0, r1, r2, r3, addr) \
    asm volatile("ldmatrix.sync.aligned.m8n8.x4.shared.b16 {%0,%1,%2,%3}, [%4];" \
                 : "=r"(r0), "=r"(r1), "=r"(r2), "=r"(r3) : "r"(addr))

__device__ __forceinline__ uint32_t bf2u(__nv_bfloat162 v) {
    return *reinterpret_cast<uint32_t*>(&v);
}

__device__ __forceinline__ void split4(float4 v, uint2& h, uint2& l) {
    __nv_bfloat162 H0 = __floats2bfloat162_rn(v.x, v.y);
    __nv_bfloat162 H1 = __floats2bfloat162_rn(v.z, v.w);
    float2 f0 = __bfloat1622float2(H0);
    float2 f1 = __bfloat1622float2(H1);
    __nv_bfloat162 L0 = __floats2bfloat162_rn(v.x - f0.x, v.y - f0.y);
    __nv_bfloat162 L1 = __floats2bfloat162_rn(v.z - f1.x, v.w - f1.y);
    h = make_uint2(bf2u(H0), bf2u(H1));
    l = make_uint2(bf2u(L0), bf2u(L1));
}

// ---------------------------------------------------------------------------
// merged elementwise tf32 pre-convert (RNA) for all five GEMM operands
// segments (float4 units): X 1M | Wq 512K | Wk 512K | Wv 512K | Wo 512K
// ---------------------------------------------------------------------------
#define N4_X  (MTOT*DMODEL/4)
#define N4_W  (D2*DMODEL/4)
#define N4_TOT (N4_X + 4*N4_W)

__global__ void cvt_all_kernel(const float* __restrict__ X,
                               const float* __restrict__ Wq, const float* __restrict__ Wk,
                               const float* __restrict__ Wv, const float* __restrict__ Wo,
                               float* __restrict__ Xt,
                               float* __restrict__ Wqt, float* __restrict__ Wkt,
                               float* __restrict__ Wvt, float* __restrict__ Wot) {
    int i = blockIdx.x * blockDim.x + threadIdx.x;
    int stride = gridDim.x * blockDim.x;
    for (; i < N4_TOT; i += stride) {
        const float* in; float* out; int j;
        if (i < N4_X)                { in = X;  out = Xt;  j = i; }
        else if (i < N4_X + N4_W)    { in = Wq; out = Wqt; j = i - N4_X; }
        else if (i < N4_X + 2*N4_W)  { in = Wk; out = Wkt; j = i - N4_X - N4_W; }
        else if (i < N4_X + 3*N4_W)  { in = Wv; out = Wvt; j = i - N4_X - 2*N4_W; }
        else                         { in = Wo; out = Wot; j = i - N4_X - 3*N4_W; }
        float4 v = ((const float4*)in)[j];
        uint4 u = make_uint4(f2tf(v.x), f2tf(v.y), f2tf(v.z), f2tf(v.w));
        ((uint4*)out)[j] = u;
    }
}

// ---------------------------------------------------------------------------
// lambda[h]
// ---------------------------------------------------------------------------
__global__ void lambda_kernel(const float* __restrict__ lq1, const float* __restrict__ lk1,
                              const float* __restrict__ lq2, const float* __restrict__ lk2) {
    int w = threadIdx.x >> 5, lane = threadIdx.x & 31;
    int base = w * 64;
    float s1 = lq1[base+lane]*lk1[base+lane] + lq1[base+32+lane]*lk1[base+32+lane];
    float s2 = lq2[base+lane]*lk2[base+lane] + lq2[base+32+lane]*lk2[base+32+lane];
    #pragma unroll
    for (int off = 16; off; off >>= 1) {
        s1 += __shfl_xor_sync(0xffffffffu, s1, off);
        s2 += __shfl_xor_sync(0xffffffffu, s2, off);
    }
    if (lane == 0) g_lam[w] = expf(s1) - expf(s2) + 0.8f;
}

// ---------------------------------------------------------------------------
// tf32 GEMM on pre-converted operands: 3-stage cp.async pipeline + ldmatrix.
// C[M,N] = A[M,K] @ W[N,K]^T (NT). 128x128x32 tile, 8 warps of 64x32.
// steady-state wait_group 1 (2 copies in flight), wait_group 0 on last iter.
// MODE 0: row-major C. MODE 1: QKV scatter.
// ---------------------------------------------------------------------------
template<int MODE>
__global__ __launch_bounds__(256, 2) void gemm_tf32(
    const float* __restrict__ A,
    const float* __restrict__ B0, const float* __restrict__ B1, const float* __restrict__ B2,
    float* __restrict__ C0, float* __restrict__ C1, float* __restrict__ C2,
    int K)
{
    extern __shared__ float gsm[];
    float* As = gsm;                  // [NSTG][SSTG]
    float* Bs = gsm + NSTG*SSTG;      // [NSTG][SSTG]

    int t = threadIdx.x;
    int wid = t >> 5, lane = t & 31;
    int row0 = blockIdx.y * 128;

    const float* Bm;
    float* C;
    int col0;
    if (MODE == 1) {
        int which = blockIdx.x >> 4;
        col0 = (blockIdx.x & 15) * 128;
        Bm = (which == 0) ? B0 : ((which == 1) ? B1 : B2);
        C  = (which == 0) ? C0 : ((which == 1) ? C1 : C2);
    } else {
        col0 = blockIdx.x * 128;
        Bm = B0; C = C0;
    }

    uint32_t a_s0 = (uint32_t)__cvta_generic_to_shared(As);
    uint32_t b_s0 = (uint32_t)__cvta_generic_to_shared(Bs);

    auto issue = [&](int s, int k0) {
        #pragma unroll
        for (int l = 0; l < 4; l++) {
            int idx = t + l*256;
            int r = idx >> 3, fq = (idx & 7) * 4;
            uint32_t da = a_s0 + (uint32_t)((s*SSTG + r*GP + fq) * 4);
            const float* sa = A + (size_t)(row0 + r) * K + k0 + fq;
            asm volatile("cp.async.cg.shared.global [%0], [%1], 16;" :: "r"(da), "l"(sa));
            uint32_t db = b_s0 + (uint32_t)((s*SSTG + r*GP + fq) * 4);
            const float* sb = Bm + (size_t)(col0 + r) * K + k0 + fq;
            asm volatile("cp.async.cg.shared.global [%0], [%1], 16;" :: "r"(db), "l"(sb));
        }
        asm volatile("cp.async.commit_group;" ::: "memory");
    };

    float acc[4][4][4];
    #pragma unroll
    for (int i = 0; i < 4; i++)
        #pragma unroll
        for (int j = 0; j < 4; j++)
            #pragma unroll
            for (int r = 0; r < 4; r++) acc[i][j][r] = 0.f;

    int wm = (wid & 1) * 64;
    int wn = (wid >> 1) * 32;
    int fr = lane >> 2;
    int fc = lane & 3;

    int row_off = lane & 7, sel = lane >> 3;
    uint32_t aA0 = a_s0 + (uint32_t)(((wm + (sel & 1) * 8 + row_off) * GP + (sel >> 1) * 4) * 4);
    uint32_t aB0 = b_s0 + (uint32_t)(((wn + (sel >> 1) * 8 + row_off) * GP + (sel & 1) * 4) * 4);

    issue(0, 0);
    if (K > 32) issue(1, 32);

    int stage = 0;
    for (int k0 = 0; k0 < K; k0 += 32) {
        bool last = (k0 + 32 >= K);
        bool more2 = (k0 + 64 < K);

        if (last) { asm volatile("cp.async.wait_group 0;" ::: "memory"); }
        else      { asm volatile("cp.async.wait_group 1;" ::: "memory"); }
        __syncthreads();                 // stage visible; all warps done with reused stage
        if (more2) {
            int ns = stage + 2; if (ns >= NSTG) ns -= NSTG;
            issue(ns, k0 + 64);
        }

        uint32_t aA = aA0 + (uint32_t)(stage * SSTG * 4);
        uint32_t aB = aB0 + (uint32_t)(stage * SSTG * 4);
        #pragma unroll
        for (int kc = 0; kc < 32; kc += 8) {
            uint32_t af[4][4], bfr[8];
            #pragma unroll
            for (int i = 0; i < 4; i++) {
                uint32_t ad = aA + (uint32_t)((i * 16 * GP + kc) * 4);
                LDSM_X4(af[i][0], af[i][1], af[i][2], af[i][3], ad);
            }
            #pragma unroll
            for (int jp = 0; jp < 2; jp++) {
                uint32_t bd = aB + (uint32_t)((jp * 16 * GP + kc) * 4);
                LDSM_X4(bfr[jp*4+0], bfr[jp*4+1], bfr[jp*4+2], bfr[jp*4+3], bd);
            }
            #pragma unroll
            for (int i = 0; i < 4; i++)
                #pragma unroll
                for (int j = 0; j < 4; j++)
                    mma_tf32(acc[i][j], af[i], &bfr[j*2]);
        }
        stage++; if (stage >= NSTG) stage = 0;
    }

    #pragma unroll
    for (int i = 0; i < 4; i++) {
        int rr = row0 + wm + i*16 + fr;
        #pragma unroll
        for (int j = 0; j < 4; j++) {
            int cc = col0 + wn + j*8 + fc*2;
            float2 v0 = make_float2(acc[i][j][0], acc[i][j][1]);
            float2 v1 = make_float2(acc[i][j][2], acc[i][j][3]);
            if (MODE == 0) {
                *(float2*)(C + (size_t)rr * DMODEL + cc) = v0;
                *(float2*)(C + (size_t)(rr + 8) * DMODEL + cc) = v1;
            } else {
                int h = cc >> 7, e = cc & 127;
                int bb = rr >> 10, n = rr & 1023;
                *(float2*)(C + (((size_t)(bb*NUM_HEADS + h) * NN + n) * DE + e)) = v0;
                int rr2 = rr + 8;
                bb = rr2 >> 10; n = rr2 & 1023;
                *(float2*)(C + (((size_t)(bb*NUM_HEADS + h) * NN + n) * DE + e)) = v1;
            }
        }
    }
}

#define GEMM_SMEM (2 * NSTG * SSTG * 4)   // 110592 bytes; 2 CTAs = 216KB <= 228KB/SM

// ---------------------------------------------------------------------------
// Dual-stream flash attention (R9-proven config, unchanged): bf16 hi/lo
// logits, V overlay via cp.async, tf32 PV, deferred l, LPT. Oc written tf32.
// ---------------------------------------------------------------------------
__global__ __launch_bounds__(256, 2) void attn_kernel(const float* __restrict__ rms_scale) {
    extern __shared__ float sm[];
    uint32_t* Qh = (uint32_t*)sm;              // 64 x WQK words
    uint32_t* Ql = Qh + 64*WQK;
    uint32_t* Kh = Ql + 64*WQK;                // union with V
    uint32_t* Kl = Kh + 64*WQK;
    float*    Vs = (float*)Kh;                 // 64 x VP raw fp32
    float*    P1 = (float*)(Kl + 64*WQK);      // 64 x PP tf32
    float*    P2 = P1 + 64*PP;
    float*   bm1 = P2 + 64*PP;
    float*   bm2 = bm1 + 128;
    float*   bs1 = bm2 + 128;
    float*   bs2 = bs1 + 128;

    int t  = threadIdx.x;
    int bh = blockIdx.y;
    int h  = bh & (NUM_HEADS - 1);
    int b  = bh >> 4;
    int qi = gridDim.x - 1 - blockIdx.x;   // LPT
    int qb = qi * 64;
    const float* Qp = g_Q + (size_t)bh * NN * DE;
    const float* Kp = g_K + (size_t)bh * NN * DE;
    const float* Vp = g_V + (size_t)bh * NN * DE;

    int lane = t & 31, wid = t >> 5;
    int gid = lane >> 2, tig = lane & 3;
    int rt = (wid >> 1) * 16;
    int half = wid & 1;
    int ch = half * 32;
    int nh = half * 64;
    int rA = rt + gid, rB = rt + gid + 8;

    uint32_t vsm0 = (uint32_t)__cvta_generic_to_shared(Vs);

    #pragma unroll
    for (int l = 0; l < 8; l++) {
        int c = t + l*256;
        int r = c >> 5, dq = (c & 31) * 4;
        float4 q = *(const float4*)(Qp + (size_t)(qb + r)*DE + dq);
        uint2 hw, lw;
        split4(q, hw, lw);
        int wi = r*WQK + (dq >> 1);
        *(uint2*)&Qh[wi] = hw;
        *(uint2*)&Ql[wi] = lw;
    }

    float m1a = -1e30f, m1b = -1e30f, m2a = -1e30f, m2b = -1e30f;
    float l1a = 0.f, l1b = 0.f, l2a = 0.f, l2b = 0.f;
    float o1[8][4], o2[8][4];
    #pragma unroll
    for (int f = 0; f < 8; f++)
        #pragma unroll
        for (int r = 0; r < 4; r++) { o1[f][r] = 0.f; o2[f][r] = 0.f; }

    float lam = g_lam[h];

    int nkb = qi + 1;
    for (int jb = 0; jb < nkb; jb++) {
        int kb = jb * 64;

        #pragma unroll
        for (int l = 0; l < 8; l++) {
            int c = t + l*256;
            int r = c >> 5, dq = (c & 31) * 4;
            float4 kq = *(const float4*)(Kp + (size_t)(kb + r)*DE + dq);
            uint2 hw, lw;
            split4(kq, hw, lw);
            int wi = r*WQK + (dq >> 1);
            *(uint2*)&Kh[wi] = hw;
            *(uint2*)&Kl[wi] = lw;
        }
        __syncthreads();

        float s1[4][4], s2[4][4];
        #pragma unroll
        for (int i = 0; i < 4; i++)
            #pragma unroll
            for (int j = 0; j < 4; j++) { s1[i][j] = 0.f; s2[i][j] = 0.f; }

        #pragma unroll
        for (int kcw = 0; kcw < 4; kcw++) {
            int wb1 = kcw * 8;
            int wb2 = 32 + kcw * 8;
            uint32_t ah[4], al[4];
            ah[0] = Qh[rA*WQK + wb1 + tig];     ah[1] = Qh[rB*WQK + wb1 + tig];
            ah[2] = Qh[rA*WQK + wb1 + 4 + tig]; ah[3] = Qh[rB*WQK + wb1 + 4 + tig];
            al[0] = Ql[rA*WQK + wb1 + tig];     al[1] = Ql[rB*WQK + wb1 + tig];
            al[2] = Ql[rA*WQK + wb1 + 4 + tig]; al[3] = Ql[rB*WQK + wb1 + 4 + tig];
            #pragma unroll
            for (int nt = 0; nt < 4; nt++) {
                int n0 = ch + nt*8 + gid;
                uint32_t bhf[2], blf[2];
                bhf[0] = Kh[n0*WQK + wb1 + tig];
                bhf[1] = Kh[n0*WQK + wb1 + 4 + tig];
                blf[0] = Kl[n0*WQK + wb1 + tig];
                blf[1] = Kl[n0*WQK + wb1 + 4 + tig];
                mma_bf16(s1[nt], ah, bhf);
                mma_bf16(s1[nt], al, bhf);
                mma_bf16(s1[nt], ah, blf);
            }
            ah[0] = Qh[rA*WQK + wb2 + tig];     ah[1] = Qh[rB*WQK + wb2 + tig];
            ah[2] = Qh[rA*WQK + wb2 + 4 + tig]; ah[3] = Qh[rB*WQK + wb2 + 4 + tig];
            al[0] = Ql[rA*WQK + wb2 + tig];     al[1] = Ql[rB*WQK + wb2 + tig];
            al[2] = Ql[rA*WQK + wb2 + 4 + tig]; al[3] = Ql[rB*WQK + wb2 + 4 + tig];
            #pragma unroll
            for (int nt = 0; nt < 4; nt++) {
                int n0 = ch + nt*8 + gid;
                uint32_t bhf[2], blf[2];
                bhf[0] = Kh[n0*WQK + wb2 + tig];
                bhf[1] = Kh[n0*WQK + wb2 + 4 + tig];
                blf[0] = Kl[n0*WQK + wb2 + tig];
                blf[1] = Kl[n0*WQK + wb2 + 4 + tig];
                mma_bf16(s2[nt], ah, bhf);
                mma_bf16(s2[nt], al, bhf);
                mma_bf16(s2[nt], ah, blf);
            }
        }

        bool last = (jb == nkb - 1);
        #pragma unroll
        for (int nt = 0; nt < 4; nt++)
            #pragma unroll
            for (int c = 0; c < 4; c++) {
                float v1 = s1[nt][c] * 0.125f;
                float v2 = s2[nt][c] * 0.125f;
                if (last) {
                    int col = ch + nt*8 + 2*tig + (c & 1);
                    int row = rt + gid + ((c & 2) ? 8 : 0);
                    if (col > row) { v1 = -1e30f; v2 = -1e30f; }
                }
                s1[nt][c] = v1; s2[nt][c] = v2;
            }

        float mt1a = -1e30f, mt1b = -1e30f, mt2a = -1e30f, mt2b = -1e30f;
        #pragma unroll
        for (int nt = 0; nt < 4; nt++) {
            mt1a = fmaxf(mt1a, fmaxf(s1[nt][0], s1[nt][1]));
            mt1b = fmaxf(mt1b, fmaxf(s1[nt][2], s1[nt][3]));
            mt2a = fmaxf(mt2a, fmaxf(s2[nt][0], s2[nt][1]));
            mt2b = fmaxf(mt2b, fmaxf(s2[nt][2], s2[nt][3]));
        }
        #pragma unroll
        for (int off = 1; off <= 2; off <<= 1) {
            mt1a = fmaxf(mt1a, __shfl_xor_sync(0xffffffffu, mt1a, off));
            mt1b = fmaxf(mt1b, __shfl_xor_sync(0xffffffffu, mt1b, off));
            mt2a = fmaxf(mt2a, __shfl_xor_sync(0xffffffffu, mt2a, off));
            mt2b = fmaxf(mt2b, __shfl_xor_sync(0xffffffffu, mt2b, off));
        }
        if (tig == 0) {
            bm1[half*64 + rA] = mt1a; bm1[half*64 + rB] = mt1b;
            bm2[half*64 + rA] = mt2a; bm2[half*64 + rB] = mt2b;
        }
        __syncthreads();

        #pragma unroll
        for (int l = 0; l < 8; l++) {
            int c = t + l*256;
            int r = c >> 5, dq = (c & 31) * 4;
            uint32_t dst = vsm0 + (uint32_t)((r*VP + dq) * 4);
            const float* src = Vp + (size_t)(kb + r)*DE + dq;
            asm volatile("cp.async.cg.shared.global [%0], [%1], 16;" :: "r"(dst), "l"(src));
        }
        asm volatile("cp.async.commit_group;" ::: "memory");

        float M1a = fmaxf(m1a, fmaxf(bm1[rA], bm1[64 + rA]));
        float M1b = fmaxf(m1b, fmaxf(bm1[rB], bm1[64 + rB]));
        float M2a = fmaxf(m2a, fmaxf(bm2[rA], bm2[64 + rA]));
        float M2b = fmaxf(m2b, fmaxf(bm2[rB], bm2[64 + rB]));
        float c1a = __expf(m1a - M1a), c1b = __expf(m1b - M1b);
        float c2a = __expf(m2a - M2a), c2b = __expf(m2b - M2b);
        m1a = M1a; m1b = M1b; m2a = M2a; m2b = M2b;

        float ps1a = 0.f, ps1b = 0.f, ps2a = 0.f, ps2b = 0.f;
        #pragma unroll
        for (int nt = 0; nt < 4; nt++) {
            int colb = ch + nt*8 + 2*tig;
            float p0 = __uint_as_float(f2tf(__expf(s1[nt][0] - M1a)));
            float p1 = __uint_as_float(f2tf(__expf(s1[nt][1] - M1a)));
            float p2 = __uint_as_float(f2tf(__expf(s1[nt][2] - M1b)));
            float p3 = __uint_as_float(f2tf(__expf(s1[nt][3] - M1b)));
            ps1a += p0 + p1; ps1b += p2 + p3;
            *(float2*)&P1[rA*PP + colb] = make_float2(p0, p1);
            *(float2*)&P1[rB*PP + colb] = make_float2(p2, p3);
            float q0 = __uint_as_float(f2tf(__expf(s2[nt][0] - M2a)));
            float q1 = __uint_as_float(f2tf(__expf(s2[nt][1] - M2a)));
            float q2 = __uint_as_float(f2tf(__expf(s2[nt][2] - M2b)));
            float q3 = __uint_as_float(f2tf(__expf(s2[nt][3] - M2b)));
            ps2a += q0 + q1; ps2b += q2 + q3;
            *(float2*)&P2[rA*PP + colb] = make_float2(q0, q1);
            *(float2*)&P2[rB*PP + colb] = make_float2(q2, q3);
        }
        l1a = l1a*c1a + ps1a;
        l1b = l1b*c1b + ps1b;
        l2a = l2a*c2a + ps2a;
        l2b = l2b*c2b + ps2b;

        asm volatile("cp.async.wait_group 0;" ::: "memory");
        __syncthreads();

        #pragma unroll
        for (int f = 0; f < 8; f++) {
            o1[f][0] *= c1a; o1[f][1] *= c1a; o1[f][2] *= c1b; o1[f][3] *= c1b;
            o2[f][0] *= c2a; o2[f][1] *= c2a; o2[f][2] *= c2b; o2[f][3] *= c2b;
        }
        #pragma unroll
        for (int kc = 0; kc < 64; kc += 8) {
            uint32_t a1f[4], a2f[4];
            a1f[0] = __float_as_uint(P1[rA*PP + kc + tig]);
            a1f[1] = __float_as_uint(P1[rB*PP + kc + tig]);
            a1f[2] = __float_as_uint(P1[rA*PP + kc + tig + 4]);
            a1f[3] = __float_as_uint(P1[rB*PP + kc + tig + 4]);
            a2f[0] = __float_as_uint(P2[rA*PP + kc + tig]);
            a2f[1] = __float_as_uint(P2[rB*PP + kc + tig]);
            a2f[2] = __float_as_uint(P2[rA*PP + kc + tig + 4]);
            a2f[3] = __float_as_uint(P2[rB*PP + kc + tig + 4]);
            #pragma unroll
            for (int f = 0; f < 8; f++) {
                uint32_t bf[2];
                bf[0] = f2tf(Vs[(kc + tig    )*VP + nh + f*8 + gid]);
                bf[1] = f2tf(Vs[(kc + tig + 4)*VP + nh + f*8 + gid]);
                mma_tf32(o1[f], a1f, bf);
                mma_tf32(o2[f], a2f, bf);
            }
        }
        __syncthreads();
    }

    #pragma unroll
    for (int off = 1; off <= 2; off <<= 1) {
        l1a += __shfl_xor_sync(0xffffffffu, l1a, off);
        l1b += __shfl_xor_sync(0xffffffffu, l1b, off);
        l2a += __shfl_xor_sync(0xffffffffu, l2a, off);
        l2b += __shfl_xor_sync(0xffffffffu, l2b, off);
    }
    if (tig == 0) {
        bs1[half*64 + rA] = l1a; bs1[half*64 + rB] = l1b;
        bs2[half*64 + rA] = l2a; bs2[half*64 + rB] = l2b;
    }
    __syncthreads();
    float il1a = 1.0f / (bs1[rA] + bs1[64 + rA]);
    float il1b = 1.0f / (bs1[rB] + bs1[64 + rB]);
    float il2a = 1.0f / (bs2[rA] + bs2[64 + rA]);
    float il2b = 1.0f / (bs2[rB] + bs2[64 + rB]);

    float ssA = 0.f, ssB = 0.f;
    #pragma unroll
    for (int f = 0; f < 8; f++) {
        o1[f][0] = o1[f][0]*il1a - lam*o2[f][0]*il2a;
        o1[f][1] = o1[f][1]*il1a - lam*o2[f][1]*il2a;
        o1[f][2] = o1[f][2]*il1b - lam*o2[f][2]*il2b;
        o1[f][3] = o1[f][3]*il1b - lam*o2[f][3]*il2b;
        ssA += o1[f][0]*o1[f][0] + o1[f][1]*o1[f][1];
        ssB += o1[f][2]*o1[f][2] + o1[f][3]*o1[f][3];
    }
    ssA += __shfl_xor_sync(0xffffffffu, ssA, 1);
    ssA += __shfl_xor_sync(0xffffffffu, ssA, 2);
    ssB += __shfl_xor_sync(0xffffffffu, ssB, 1);
    ssB += __shfl_xor_sync(0xffffffffu, ssB, 2);

    if (tig == 0) {
        float* dst = half ? bm2 : bm1;
        dst[rA] = ssA;
        dst[rB] = ssB;
    }
    __syncthreads();
    float totA = bm1[rA] + bm2[rA];
    float totB = bm1[rB] + bm2[rB];
    float scA = rsqrtf(totA * (1.0f/128.0f) + 1e-5f) * 0.2f;
    float scB = rsqrtf(totB * (1.0f/128.0f) + 1e-5f) * 0.2f;

    // write Oc pre-rounded to tf32 (bit-identical to cvt-at-store)
    size_t obaseA = ((size_t)b * NN + qb + rA) * D2 + h * DE;
    size_t obaseB = ((size_t)b * NN + qb + rB) * D2 + h * DE;
    #pragma unroll
    for (int f = 0; f < 8; f++) {
        int col = nh + f*8 + 2*tig;
        float2 rs = *(const float2*)(rms_scale + col);
        uint2 wA = make_uint2(f2tf(o1[f][0]*scA*rs.x), f2tf(o1[f][1]*scA*rs.y));
        uint2 wB = make_uint2(f2tf(o1[f][2]*scB*rs.x), f2tf(o1[f][3]*scB*rs.y));
        *(uint2*)(g_Oc + obaseA + col) = wA;
        *(uint2*)(g_Oc + obaseB + col) = wB;
    }
}

#define ATTN_SMEM (26624 * 4)   // 106496 bytes -> 2 blocks/SM

extern "C" void kernel_launch(void* const* d_in, const int* in_sizes, int n_in,
                              void* d_out, int out_size) {
    const float* X   = (const float*)d_in[0];
    const float* Wq  = (const float*)d_in[1];
    const float* Wk  = (const float*)d_in[2];
    const float* Wv  = (const float*)d_in[3];
    const float* Wo  = (const float*)d_in[4];
    const float* lq1 = (const float*)d_in[5];
    const float* lk1 = (const float*)d_in[6];
    const float* lq2 = (const float*)d_in[7];
    const float* lk2 = (const float*)d_in[8];
    const float* rms = (const float*)d_in[9];

    float *pQ, *pK, *pV, *pOc, *pXt, *pWqt, *pWkt, *pWvt, *pWot;
    cudaGetSymbolAddress((void**)&pQ,   g_Q);
    cudaGetSymbolAddress((void**)&pK,   g_K);
    cudaGetSymbolAddress((void**)&pV,   g_V);
    cudaGetSymbolAddress((void**)&pOc,  g_Oc);
    cudaGetSymbolAddress((void**)&pXt,  g_Xt);
    cudaGetSymbolAddress((void**)&pWqt, g_Wqt);
    cudaGetSymbolAddress((void**)&pWkt, g_Wkt);
    cudaGetSymbolAddress((void**)&pWvt, g_Wvt);
    cudaGetSymbolAddress((void**)&pWot, g_Wot);

    lambda_kernel<<<1, 512>>>(lq1, lk1, lq2, lk2);

    cvt_all_kernel<<<1184, 256>>>(X, Wq, Wk, Wv, Wo, pXt, pWqt, pWkt, pWvt, pWot);

    cudaFuncSetAttribute(gemm_tf32<1>, cudaFuncAttributeMaxDynamicSharedMemorySize, GEMM_SMEM);
    cudaFuncSetAttribute(gemm_tf32<0>, cudaFuncAttributeMaxDynamicSharedMemorySize, GEMM_SMEM);

    dim3 gqkv(48, MTOT/128);
    gemm_tf32<1><<<gqkv, 256, GEMM_SMEM>>>(pXt, pWqt, pWkt, pWvt, pQ, pK, pV, DMODEL);

    cudaFuncSetAttribute(attn_kernel, cudaFuncAttributeMaxDynamicSharedMemorySize, ATTN_SMEM);
    attn_kernel<<<dim3(NN/64, BB*NUM_HEADS), 256, ATTN_SMEM>>>(rms);

    dim3 gout(DMODEL/128, MTOT/128);
    gemm_tf32<0><<<gout, 256, GEMM_SMEM>>>(pOc, pWot, nullptr, nullptr, (float*)d_out, nullptr, nullptr, D2);
}